// round 10
// baseline (speedup 1.0000x reference)
#include <cuda_runtime.h>
#include <math.h>
#include <stdint.h>

#define B_  1024
#define S_  256
#define H_  1024
#define E_  16
#define K_  4
#define HE_ 256
#define C_  3

// ---------------- device scratch ---------------------------------------------
__device__ float g_pooled[B_*H_];
__device__ float g_t[B_*H_];
__device__ float g_orig[B_*C_];
__device__ int   g_topi[B_*K_];
__device__ float g_topw[B_*K_];
__device__ int   g_cnt[E_];
__device__ int   g_tok[E_*B_];
__device__ int   g_slot[E_*B_];
__device__ float g_el[B_*K_*C_];
__device__ float g_M[E_*C_*HE_];      // collapsed proj @ eW2
__device__ float g_pb2[E_*C_];        // collapsed bias

// ---------------- cp.async helpers -------------------------------------------
__device__ __forceinline__ void cp16(void* dst, const void* src){
    unsigned d = (unsigned)__cvta_generic_to_shared(dst);
    asm volatile("cp.async.cg.shared.global [%0], [%1], 16;\n" :: "r"(d), "l"(src));
}
__device__ __forceinline__ void cp_commit(){ asm volatile("cp.async.commit_group;\n" ::); }
__device__ __forceinline__ void cp_wait1(){ asm volatile("cp.async.wait_group 1;\n" ::); }
__device__ __forceinline__ void cp_wait0(){ asm volatile("cp.async.wait_group 0;\n" ::); }

// ---------------- tf32 mma + in-register split -------------------------------
__device__ __forceinline__ void mma_tf32(float* c, const unsigned* a, const unsigned* b){
    asm volatile("mma.sync.aligned.m16n8k8.row.col.f32.tf32.tf32.f32 "
        "{%0,%1,%2,%3},{%4,%5,%6,%7},{%8,%9},{%0,%1,%2,%3};\n"
        : "+f"(c[0]), "+f"(c[1]), "+f"(c[2]), "+f"(c[3])
        : "r"(a[0]), "r"(a[1]), "r"(a[2]), "r"(a[3]), "r"(b[0]), "r"(b[1]));
}

__device__ __forceinline__ void splitf(float a, unsigned& hi, unsigned& lo){
    unsigned u = __float_as_uint(a) & 0xffffe000u;
    hi = u;
    lo = __float_as_uint(a - __uint_as_float(u));
}

// warp tile 32(m) x 32(n), BK=32, raw fp32 smem tiles (stride 36), 3xTF32.
__device__ __forceinline__ void compute_raw(const float* __restrict__ As,
                                            const float* __restrict__ Bs,
                                            int wmBase, int wnBase, int lane,
                                            float (&acc)[2][4][4]){
    int g = lane >> 2, q = lane & 3;
    #pragma unroll
    for (int kk = 0; kk < 32; kk += 8){
        unsigned ah[2][4], al[2][4], bh[4][2], bl[4][2];
        #pragma unroll
        for (int mf = 0; mf < 2; mf++){
            int r = wmBase + mf*16 + g;
            const float* p = As + r*36 + kk + q;
            splitf(p[0],      ah[mf][0], al[mf][0]);
            splitf(p[8*36],   ah[mf][1], al[mf][1]);
            splitf(p[4],      ah[mf][2], al[mf][2]);
            splitf(p[8*36+4], ah[mf][3], al[mf][3]);
        }
        #pragma unroll
        for (int nf = 0; nf < 4; nf++){
            int nn = wnBase + nf*8 + g;
            const float* p = Bs + nn*36 + kk + q;
            splitf(p[0], bh[nf][0], bl[nf][0]);
            splitf(p[4], bh[nf][1], bl[nf][1]);
        }
        #pragma unroll
        for (int mf = 0; mf < 2; mf++)
            #pragma unroll
            for (int nf = 0; nf < 4; nf++){
                mma_tf32(acc[mf][nf], ah[mf], bh[nf]);
                mma_tf32(acc[mf][nf], ah[mf], bl[nf]);
                mma_tf32(acc[mf][nf], al[mf], bh[nf]);
            }
    }
}

// warp tile 16(m) x 32(n); A stride 36.
__device__ __forceinline__ void compute16(const float* __restrict__ Asl,
                                          const float* __restrict__ Bs,
                                          int wnBase, int lane, float (&acc)[4][4]){
    int g = lane >> 2, q = lane & 3;
    #pragma unroll
    for (int kk = 0; kk < 32; kk += 8){
        unsigned ah[4], al[4], bh[4][2], bl[4][2];
        const float* p = Asl + g*36 + kk + q;
        splitf(p[0],      ah[0], al[0]);
        splitf(p[8*36],   ah[1], al[1]);
        splitf(p[4],      ah[2], al[2]);
        splitf(p[8*36+4], ah[3], al[3]);
        #pragma unroll
        for (int nf = 0; nf < 4; nf++){
            const float* pb = Bs + (wnBase + nf*8 + g)*36 + kk + q;
            splitf(pb[0], bh[nf][0], bl[nf][0]);
            splitf(pb[4], bh[nf][1], bl[nf][1]);
        }
        #pragma unroll
        for (int nf = 0; nf < 4; nf++){
            mma_tf32(acc[nf], ah, bh[nf]);
            mma_tf32(acc[nf], ah, bl[nf]);
            mma_tf32(acc[nf], al, bh[nf]);
        }
    }
}

// ---------------- 1) pooled mean ---------------------------------------------
__global__ void __launch_bounds__(256) pool_kernel(const float* __restrict__ hid){
    int b = blockIdx.x;
    const float4* p = reinterpret_cast<const float4*>(hid + (size_t)b*S_*H_) + threadIdx.x;
    float4 a0 = {0.f,0.f,0.f,0.f}, a1 = {0.f,0.f,0.f,0.f};
    float4 a2 = {0.f,0.f,0.f,0.f}, a3 = {0.f,0.f,0.f,0.f};
    #pragma unroll 4
    for (int s=0; s<S_; s+=4){
        float4 v0 = p[(size_t)(s+0)*(H_/4)];
        float4 v1 = p[(size_t)(s+1)*(H_/4)];
        float4 v2 = p[(size_t)(s+2)*(H_/4)];
        float4 v3 = p[(size_t)(s+3)*(H_/4)];
        a0.x+=v0.x; a0.y+=v0.y; a0.z+=v0.z; a0.w+=v0.w;
        a1.x+=v1.x; a1.y+=v1.y; a1.z+=v1.z; a1.w+=v1.w;
        a2.x+=v2.x; a2.y+=v2.y; a2.z+=v2.z; a2.w+=v2.w;
        a3.x+=v3.x; a3.y+=v3.y; a3.z+=v3.z; a3.w+=v3.w;
    }
    float4 r;
    r.x=((a0.x+a1.x)+(a2.x+a3.x))*(1.f/S_);
    r.y=((a0.y+a1.y)+(a2.y+a3.y))*(1.f/S_);
    r.z=((a0.z+a1.z)+(a2.z+a3.z))*(1.f/S_);
    r.w=((a0.w+a1.w)+(a2.w+a3.w))*(1.f/S_);
    reinterpret_cast<float4*>(g_pooled + (size_t)b*H_)[threadIdx.x] = r;
}

// ---------------- 2) router + top-4 + softmax --------------------------------
__global__ void __launch_bounds__(512) router_topk_kernel(const float* __restrict__ hid,
                                                          const float* __restrict__ rW,
                                                          const float* __restrict__ rb){
    __shared__ float cls[H_];
    __shared__ float lg[E_];
    int b = blockIdx.x, tid = threadIdx.x;
    cls[tid]       = hid[(size_t)b*S_*H_ + tid];
    cls[tid + 512] = hid[(size_t)b*S_*H_ + tid + 512];
    __syncthreads();
    int w = tid >> 5, lane = tid & 31;
    float s = 0.f;
    const float* wr = rW + w*H_;
    #pragma unroll 8
    for (int j=lane; j<H_; j+=32) s += cls[j]*wr[j];
    #pragma unroll
    for (int o=16;o>0;o>>=1) s += __shfl_xor_sync(0xffffffffu, s, o);
    if (lane==0) lg[w] = s + rb[w];
    __syncthreads();
    if (tid==0){
        float v[E_];
        #pragma unroll
        for (int i=0;i<E_;i++) v[i]=lg[i];
        int   idxs[K_]; float vals[K_];
        for (int k=0;k<K_;k++){
            int bi=0; float bv=-3.0e38f;
            #pragma unroll
            for (int i=0;i<E_;i++){ if (v[i]>bv){ bv=v[i]; bi=i; } }
            idxs[k]=bi; vals[k]=bv; v[bi]=-3.0e38f;
        }
        float m = vals[0], ssum=0.f, wv[K_];
        for (int k=0;k<K_;k++){ wv[k]=expf(vals[k]-m); ssum+=wv[k]; }
        float inv = 1.f/ssum;
        for (int k=0;k<K_;k++){ g_topi[b*K_+k]=idxs[k]; g_topw[b*K_+k]=wv[k]*inv; }
    }
}

// ---------------- 3) gather (single block, smem counters) --------------------
__global__ void __launch_bounds__(1024) gather_kernel(){
    __shared__ int cnt[E_];
    int t = threadIdx.x;
    if (t < E_) cnt[t] = 0;
    __syncthreads();
    #pragma unroll
    for (int i=0;i<4;i++){
        int idx = t + i*1024;
        int e = g_topi[idx];
        int pos = atomicAdd(&cnt[e], 1);
        g_tok [e*B_+pos] = idx >> 2;
        g_slot[e*B_+pos] = idx & 3;
    }
    __syncthreads();
    if (t < E_) g_cnt[t] = cnt[t];
}

// ---------------- 3b) precompute M_e = pW @ eW2[e], pb2 = pW @ eb2[e] + pb ---
// 1024 threads: oc = t>>8 splits the 256-deep o-reduction 4 ways; smem reduce.
__global__ void __launch_bounds__(1024) precompute_M_kernel(const float* __restrict__ eW2,
                                                            const float* __restrict__ eb2,
                                                            const float* __restrict__ pW,
                                                            const float* __restrict__ pb){
    __shared__ float red[C_][4][HE_];
    int e = blockIdx.x;
    int t = threadIdx.x;
    int oc = t >> 8, h = t & (HE_-1);
    const float* w2 = eW2 + (size_t)e*HE_*HE_;
    float m0=0.f, m1=0.f, m2=0.f;
    #pragma unroll 8
    for (int i=0;i<HE_/4;i++){
        int o = oc*(HE_/4) + i;
        float v = w2[(size_t)o*HE_ + h];
        m0 += pW[0*HE_+o]*v;
        m1 += pW[1*HE_+o]*v;
        m2 += pW[2*HE_+o]*v;
    }
    red[0][oc][h]=m0; red[1][oc][h]=m1; red[2][oc][h]=m2;
    __syncthreads();
    if (t < HE_){
        #pragma unroll
        for (int c=0;c<C_;c++)
            g_M[(e*C_+c)*HE_+t] = (red[c][0][t]+red[c][1][t])+(red[c][2][t]+red[c][3][t]);
    } else if (t >= HE_ && t < HE_+C_){
        int c = t - HE_;
        float s = pb[c];
        #pragma unroll 8
        for (int o=0;o<HE_;o++) s += pW[c*HE_+o]*eb2[e*HE_+o];
        g_pb2[e*C_+c] = s;
    }
}

// ---------------- 4) dense head: t = tanh(cls @ dW^T + db) -------------------
__global__ void __launch_bounds__(128) dense_tanh_kernel(const float* __restrict__ hid,
                                                         const float* __restrict__ W,
                                                         const float* __restrict__ bias){
    __shared__ float As[2][64*36];
    __shared__ float Bs[2][64*36];
    int t = threadIdx.x, lane = t & 31, warp = t >> 5;
    int wm = warp >> 1, wn = warp & 1;
    int m0 = blockIdx.y*64, n0 = blockIdx.x*64;
    int lr = t >> 3, lc = (t & 7)*4;
    float acc[2][4][4];
    #pragma unroll
    for (int i=0;i<2;i++)
        #pragma unroll
        for (int j=0;j<4;j++)
            #pragma unroll
            for (int k=0;k<4;k++) acc[i][j][k]=0.f;

    auto load = [&](int s, int k0){
        #pragma unroll
        for (int i=0;i<4;i++){
            int row = lr + 16*i;
            cp16(&As[s][row*36+lc], hid + (size_t)(m0+row)*S_*H_ + k0 + lc);
            cp16(&Bs[s][row*36+lc], W   + (size_t)(n0+row)*H_   + k0 + lc);
        }
    };
    load(0, 0); cp_commit();
    for (int it=0; it<32; it++){
        if (it+1 < 32){ load((it+1)&1, (it+1)*32); cp_commit(); cp_wait1(); }
        else cp_wait0();
        __syncthreads();
        compute_raw(As[it&1], Bs[it&1], wm*32, wn*32, lane, acc);
        __syncthreads();
    }
    int g = lane>>2, q = lane&3;
    #pragma unroll
    for (int nf=0;nf<4;nf++){
        int col = n0 + wn*32 + nf*8 + 2*q;
        float2 bb = *(const float2*)&bias[col];
        #pragma unroll
        for (int mf=0;mf<2;mf++){
            int row = m0 + wm*32 + mf*16 + g;
            float2 o0, o1;
            o0.x = tanhf(acc[mf][nf][0]+bb.x); o0.y = tanhf(acc[mf][nf][1]+bb.y);
            o1.x = tanhf(acc[mf][nf][2]+bb.x); o1.y = tanhf(acc[mf][nf][3]+bb.y);
            *(float2*)&g_t[(size_t)row*H_ + col]     = o0;
            *(float2*)&g_t[(size_t)(row+8)*H_ + col] = o1;
        }
    }
}

// ---------------- 5) orig = t @ out_W^T + out_b ------------------------------
__global__ void __launch_bounds__(256) orig_kernel(const float* __restrict__ oW,
                                                   const float* __restrict__ ob){
    int w = threadIdx.x >> 5, lane = threadIdx.x & 31;
    int b = blockIdx.x*8 + w;
    const float* t = g_t + (size_t)b*H_;
    for (int c=0;c<C_;c++){
        float s=0.f;
        const float* wr = oW + c*H_;
        #pragma unroll 8
        for (int j=lane; j<H_; j+=32) s += t[j]*wr[j];
        #pragma unroll
        for (int o=16;o>0;o>>=1) s += __shfl_xor_sync(0xffffffffu, s, o);
        if (lane==0) g_orig[b*C_+c] = s + ob[c];
    }
}

// ---------------- 6) fused expert: GEMM1 + LN + GELU + collapsed proj --------
// 16 gathered rows x 256 cols per block; 256 threads (8 warps, warp 16x32).
__global__ void __launch_bounds__(256) expert_fused_kernel(const float* __restrict__ eW1,
                                                           const float* __restrict__ eb1,
                                                           const float* __restrict__ eg,
                                                           const float* __restrict__ ebt){
    extern __shared__ float sm[];
    float* As0 = sm;                    // 16*36
    float* As1 = sm + 576;
    float* Bs0 = sm + 1152;             // 256*36
    float* Bs1 = sm + 1152 + 9216;
    float* Cs  = sm + 19584;            // 16 x 260
    __shared__ int toks[16], slots[16];
    int e = blockIdx.y;
    int n = g_cnt[e];
    int r0 = blockIdx.x*16;
    if (r0 >= n) return;
    int t = threadIdx.x, lane = t & 31, warp = t >> 5;
    if (t < 16){
        int rc = min(r0 + t, n-1);
        toks[t]  = g_tok [e*B_+rc];
        slots[t] = g_slot[e*B_+rc];
    }
    __syncthreads();
    int lr = t >> 3, lc = (t & 7)*4;    // B rows lr+32i; A (t<128) row lr in 0..15
    float acc[4][4];
    #pragma unroll
    for (int i=0;i<4;i++)
        #pragma unroll
        for (int j=0;j<4;j++) acc[i][j]=0.f;

    const float* w1 = eW1 + (size_t)e*HE_*H_;
    const float* arow = g_pooled + (size_t)toks[lr & 15]*H_ + lc;
    auto load1 = [&](float* Asb, float* Bsb, int k0){
        if (t < 128) cp16(&Asb[lr*36+lc], arow + k0);
        #pragma unroll
        for (int i=0;i<8;i++){
            int row = lr + 32*i;
            cp16(&Bsb[row*36+lc], w1 + (size_t)row*H_ + k0 + lc);
        }
    };
    // ---- phase 1 mainloop (K=1024, 32 iters, 2-stage) ----
    load1(As0, Bs0, 0); cp_commit();
    for (int it=0; it<32; it++){
        if (it+1 < 32){
            if ((it+1)&1) load1(As1, Bs1, (it+1)*32); else load1(As0, Bs0, (it+1)*32);
            cp_commit(); cp_wait1();
        } else cp_wait0();
        __syncthreads();
        if (it&1) compute16(As1, Bs1, warp*32, lane, acc);
        else      compute16(As0, Bs0, warp*32, lane, acc);
        __syncthreads();
    }
    // ---- stage C tile into Cs ----
    int g = lane>>2, q = lane&3;
    #pragma unroll
    for (int nf=0;nf<4;nf++){
        int col = warp*32 + nf*8 + 2*q;
        float2 a; a.x=acc[nf][0]; a.y=acc[nf][1];
        float2 b; b.x=acc[nf][2]; b.y=acc[nf][3];
        *(float2*)&Cs[g*260 + col]     = a;
        *(float2*)&Cs[(g+8)*260 + col] = b;
    }
    __syncthreads();
    // ---- LN + GELU in place: 16 threads per row, 16 cols each ----
    {
        int row = t >> 4, j = t & 15;
        const float* b1 = eb1 + e*HE_;
        float s = 0.f, qs = 0.f;
        #pragma unroll
        for (int cc=0; cc<16; cc+=4){
            float4 v = *(float4*)&Cs[row*260 + j*16 + cc];
            float4 bb = *(const float4*)&b1[j*16 + cc];
            v.x+=bb.x; v.y+=bb.y; v.z+=bb.z; v.w+=bb.w;
            s  += v.x+v.y+v.z+v.w;
            qs += v.x*v.x+v.y*v.y+v.z*v.z+v.w*v.w;
        }
        #pragma unroll
        for (int o=1;o<16;o<<=1){
            s  += __shfl_xor_sync(0xffffffffu, s,  o);
            qs += __shfl_xor_sync(0xffffffffu, qs, o);
        }
        float m = s*(1.f/HE_);
        float var = qs*(1.f/HE_) - m*m;
        float rstd = rsqrtf(var + 1e-5f);
        const float* gp = eg  + e*HE_;
        const float* bp = ebt + e*HE_;
        #pragma unroll
        for (int cc=0; cc<16; cc+=4){
            float4 v = *(float4*)&Cs[row*260 + j*16 + cc];
            float4 bb = *(const float4*)&b1[j*16 + cc];
            float4 gg = *(const float4*)&gp[j*16 + cc];
            float4 bt = *(const float4*)&bp[j*16 + cc];
            float z0 = (v.x+bb.x-m)*rstd*gg.x + bt.x;
            float z1 = (v.y+bb.y-m)*rstd*gg.y + bt.y;
            float z2 = (v.z+bb.z-m)*rstd*gg.z + bt.z;
            float z3 = (v.w+bb.w-m)*rstd*gg.w + bt.w;
            float4 o;
            o.x = 0.5f*z0*(1.f+erff(z0*0.70710678118654752f));
            o.y = 0.5f*z1*(1.f+erff(z1*0.70710678118654752f));
            o.z = 0.5f*z2*(1.f+erff(z2*0.70710678118654752f));
            o.w = 0.5f*z3*(1.f+erff(z3*0.70710678118654752f));
            *(float4*)&Cs[row*260 + j*16 + cc] = o;
        }
    }
    __syncthreads();
    // ---- collapsed proj epilogue: el = M_e @ hgelu + pb2 ----
    {
        int row = t >> 4, j = t & 15;
        int gr = r0 + row;
        const float* M0 = g_M + (e*C_+0)*HE_;
        const float* M1 = g_M + (e*C_+1)*HE_;
        const float* M2 = g_M + (e*C_+2)*HE_;
        float p0=0.f, p1=0.f, p2=0.f;
        #pragma unroll
        for (int cc=0; cc<16; cc+=4){
            float4 v = *(float4*)&Cs[row*260 + j*16 + cc];
            float4 w0 = *(const float4*)&M0[j*16 + cc];
            float4 w1 = *(const float4*)&M1[j*16 + cc];
            float4 w2 = *(const float4*)&M2[j*16 + cc];
            p0 += v.x*w0.x + v.y*w0.y + v.z*w0.z + v.w*w0.w;
            p1 += v.x*w1.x + v.y*w1.y + v.z*w1.z + v.w*w1.w;
            p2 += v.x*w2.x + v.y*w2.y + v.z*w2.z + v.w*w2.w;
        }
        #pragma unroll
        for (int o=1;o<16;o<<=1){
            p0 += __shfl_xor_sync(0xffffffffu, p0, o);
            p1 += __shfl_xor_sync(0xffffffffu, p1, o);
            p2 += __shfl_xor_sync(0xffffffffu, p2, o);
        }
        if (j == 0 && gr < n){
            int b = toks[row], sl = slots[row];
            float* o = &g_el[(b*K_+sl)*C_];
            o[0] = p0 + g_pb2[e*C_+0];
            o[1] = p1 + g_pb2[e*C_+1];
            o[2] = p2 + g_pb2[e*C_+2];
        }
    }
}

// ---------------- 8) final head ---------------------------------------------
__global__ void __launch_bounds__(256) final_kernel(const float* __restrict__ f1W,
                                                    const float* __restrict__ f1b,
                                                    const float* __restrict__ fg,
                                                    const float* __restrict__ fbt,
                                                    const float* __restrict__ f2W,
                                                    const float* __restrict__ f2b,
                                                    float* __restrict__ out){
    int b = blockIdx.x*blockDim.x + threadIdx.x;
    if (b >= B_) return;
    float comb[2*C_];
    #pragma unroll
    for (int c=0;c<C_;c++) comb[c] = g_orig[b*C_+c];
    float moe[C_]={0.f,0.f,0.f};
    #pragma unroll
    for (int k=0;k<K_;k++){
        float w = g_topw[b*K_+k];
        const float* el = &g_el[(b*K_+k)*C_];
        #pragma unroll
        for (int c=0;c<C_;c++) moe[c] += w*el[c];
    }
    #pragma unroll
    for (int c=0;c<C_;c++) comb[C_+c]=moe[c];
    float y[C_];
    #pragma unroll
    for (int c=0;c<C_;c++){
        float s = f1b[c];
        #pragma unroll
        for (int jj=0;jj<2*C_;jj++) s += comb[jj]*f1W[c*(2*C_)+jj];
        y[c]=s;
    }
    float m = (y[0]+y[1]+y[2])*(1.f/3.f);
    float d0=y[0]-m, d1=y[1]-m, d2=y[2]-m;
    float var = (d0*d0+d1*d1+d2*d2)*(1.f/3.f);
    float rs = rsqrtf(var + 1e-5f);
    float z[C_];
    #pragma unroll
    for (int c=0;c<C_;c++) z[c] = fmaxf(0.f, (y[c]-m)*rs*fg[c] + fbt[c]);
    #pragma unroll
    for (int c2=0;c2<C_;c2++){
        float s = f2b[c2];
        #pragma unroll
        for (int c=0;c<C_;c++) s += z[c]*f2W[c2*C_+c];
        out[b*C_+c2] = s;
    }
}

// ---------------- streams/events (host-side objects, created once) -----------
struct SideStreams {
    cudaStream_t sB, sC, sD;
    cudaEvent_t  evFork, evJB, evJC, evPre;
    SideStreams(){
        cudaStreamCreateWithFlags(&sB, cudaStreamNonBlocking);
        cudaStreamCreateWithFlags(&sC, cudaStreamNonBlocking);
        cudaStreamCreateWithFlags(&sD, cudaStreamNonBlocking);
        cudaEventCreateWithFlags(&evFork, cudaEventDisableTiming);
        cudaEventCreateWithFlags(&evJB,   cudaEventDisableTiming);
        cudaEventCreateWithFlags(&evJC,   cudaEventDisableTiming);
        cudaEventCreateWithFlags(&evPre,  cudaEventDisableTiming);
    }
};
static SideStreams g_ss;

// ---------------- launch -----------------------------------------------------
extern "C" void kernel_launch(void* const* d_in, const int* in_sizes, int n_in,
                              void* d_out, int out_size){
    const float* hid = (const float*)d_in[0];
    const float* rW  = (const float*)d_in[1];
    const float* rb  = (const float*)d_in[2];
    const float* eW1 = (const float*)d_in[3];
    const float* eb1 = (const float*)d_in[4];
    const float* eg  = (const float*)d_in[5];
    const float* ebt = (const float*)d_in[6];
    const float* eW2 = (const float*)d_in[7];
    const float* eb2 = (const float*)d_in[8];
    const float* pW  = (const float*)d_in[9];
    const float* pb  = (const float*)d_in[10];
    const float* dW  = (const float*)d_in[11];
    const float* db  = (const float*)d_in[12];
    const float* oW  = (const float*)d_in[13];
    const float* ob  = (const float*)d_in[14];
    const float* f1W = (const float*)d_in[15];
    const float* f1b = (const float*)d_in[16];
    const float* fg  = (const float*)d_in[17];
    const float* fbt = (const float*)d_in[18];
    const float* f2W = (const float*)d_in[19];
    const float* f2b = (const float*)d_in[20];
    float* out = (float*)d_out;

    const int DSM_EXP = (2*16*36 + 2*256*36 + 16*260)*4;  // 94976 B
    cudaFuncSetAttribute(expert_fused_kernel, cudaFuncAttributeMaxDynamicSharedMemorySize, DSM_EXP);

    // fork branches
    cudaEventRecord(g_ss.evFork, 0);
    cudaStreamWaitEvent(g_ss.sB, g_ss.evFork, 0);
    cudaStreamWaitEvent(g_ss.sC, g_ss.evFork, 0);
    cudaStreamWaitEvent(g_ss.sD, g_ss.evFork, 0);

    // main stream: HBM-bound pool (critical path)
    pool_kernel<<<B_, 256>>>(hid);

    // branch B: router + gather
    router_topk_kernel<<<B_, 512, 0, g_ss.sB>>>(hid, rW, rb);
    gather_kernel<<<1, 1024, 0, g_ss.sB>>>();
    cudaEventRecord(g_ss.evJB, g_ss.sB);

    // branch C: dense head + orig (starts immediately)
    dense_tanh_kernel<<<dim3(16,16), 128, 0, g_ss.sC>>>(hid, dW, db);
    orig_kernel<<<B_/8, 256, 0, g_ss.sC>>>(oW, ob);
    cudaEventRecord(g_ss.evJC, g_ss.sC);

    // branch D: collapsed proj precompute (weights-only, hidden under pool)
    precompute_M_kernel<<<E_, 1024, 0, g_ss.sD>>>(eW2, eb2, pW, pb);
    cudaEventRecord(g_ss.evPre, g_ss.sD);

    // join B + precompute before fused expert kernel
    cudaStreamWaitEvent(0, g_ss.evJB, 0);
    cudaStreamWaitEvent(0, g_ss.evPre, 0);
    expert_fused_kernel<<<dim3(B_/16, E_), 256, DSM_EXP>>>(eW1, eb1, eg, ebt);

    // join C before final head
    cudaStreamWaitEvent(0, g_ss.evJC, 0);
    final_kernel<<<B_/256, 256>>>(f1W, f1b, fg, fbt, f2W, f2b, out);
}

// round 11
// speedup vs baseline: 1.0403x; 1.0403x over previous
#include <cuda_runtime.h>
#include <math.h>
#include <stdint.h>

#define B_  1024
#define S_  256
#define H_  1024
#define E_  16
#define K_  4
#define HE_ 256
#define C_  3

// ---------------- device scratch ---------------------------------------------
__device__ float g_pooled[B_*H_];
__device__ float g_t[B_*H_];
__device__ float g_orig[B_*C_];
__device__ int   g_topi[B_*K_];
__device__ float g_topw[B_*K_];
__device__ int   g_cnt[E_];
__device__ int   g_tok[E_*B_];
__device__ int   g_slot[E_*B_];
__device__ float g_el[B_*K_*C_];

// ---------------- cp.async helpers -------------------------------------------
__device__ __forceinline__ void cp16(void* dst, const void* src){
    unsigned d = (unsigned)__cvta_generic_to_shared(dst);
    asm volatile("cp.async.cg.shared.global [%0], [%1], 16;\n" :: "r"(d), "l"(src));
}
__device__ __forceinline__ void cp_commit(){ asm volatile("cp.async.commit_group;\n" ::); }
__device__ __forceinline__ void cp_wait1(){ asm volatile("cp.async.wait_group 1;\n" ::); }
__device__ __forceinline__ void cp_wait0(){ asm volatile("cp.async.wait_group 0;\n" ::); }

// ---------------- tf32 mma + in-register split -------------------------------
__device__ __forceinline__ void mma_tf32(float* c, const unsigned* a, const unsigned* b){
    asm volatile("mma.sync.aligned.m16n8k8.row.col.f32.tf32.tf32.f32 "
        "{%0,%1,%2,%3},{%4,%5,%6,%7},{%8,%9},{%0,%1,%2,%3};\n"
        : "+f"(c[0]), "+f"(c[1]), "+f"(c[2]), "+f"(c[3])
        : "r"(a[0]), "r"(a[1]), "r"(a[2]), "r"(a[3]), "r"(b[0]), "r"(b[1]));
}

__device__ __forceinline__ void splitf(float a, unsigned& hi, unsigned& lo){
    unsigned u = __float_as_uint(a) & 0xffffe000u;
    hi = u;
    lo = __float_as_uint(a - __uint_as_float(u));
}

// warp tile 32(m) x 32(n), BK=32, raw fp32 smem tiles (stride 36), 3xTF32.
// ILP-split accumulators: accH gets hi*hi, accL gets hi*lo + lo*hi.
__device__ __forceinline__ void compute_raw(const float* __restrict__ As,
                                            const float* __restrict__ Bs,
                                            int wmBase, int wnBase, int lane,
                                            float (&accH)[2][4][4],
                                            float (&accL)[2][4][4]){
    int g = lane >> 2, q = lane & 3;
    #pragma unroll
    for (int kk = 0; kk < 32; kk += 8){
        unsigned ah[2][4], al[2][4], bh[4][2], bl[4][2];
        #pragma unroll
        for (int mf = 0; mf < 2; mf++){
            int r = wmBase + mf*16 + g;
            const float* p = As + r*36 + kk + q;
            splitf(p[0],      ah[mf][0], al[mf][0]);
            splitf(p[8*36],   ah[mf][1], al[mf][1]);
            splitf(p[4],      ah[mf][2], al[mf][2]);
            splitf(p[8*36+4], ah[mf][3], al[mf][3]);
        }
        #pragma unroll
        for (int nf = 0; nf < 4; nf++){
            int nn = wnBase + nf*8 + g;
            const float* p = Bs + nn*36 + kk + q;
            splitf(p[0], bh[nf][0], bl[nf][0]);
            splitf(p[4], bh[nf][1], bl[nf][1]);
        }
        #pragma unroll
        for (int mf = 0; mf < 2; mf++)
            #pragma unroll
            for (int nf = 0; nf < 4; nf++){
                mma_tf32(accH[mf][nf], ah[mf], bh[nf]);
                mma_tf32(accL[mf][nf], ah[mf], bl[nf]);
                mma_tf32(accL[mf][nf], al[mf], bh[nf]);
            }
    }
}

// warp tile 16(m) x 32(n); A stride templated (36 staged, 260 for Cs). ILP-split.
template<int AS>
__device__ __forceinline__ void compute16(const float* __restrict__ Asl,
                                          const float* __restrict__ Bs,
                                          int wnBase, int lane,
                                          float (&accH)[4][4], float (&accL)[4][4]){
    int g = lane >> 2, q = lane & 3;
    #pragma unroll
    for (int kk = 0; kk < 32; kk += 8){
        unsigned ah[4], al[4], bh[4][2], bl[4][2];
        const float* p = Asl + g*AS + kk + q;
        splitf(p[0],      ah[0], al[0]);
        splitf(p[8*AS],   ah[1], al[1]);
        splitf(p[4],      ah[2], al[2]);
        splitf(p[8*AS+4], ah[3], al[3]);
        #pragma unroll
        for (int nf = 0; nf < 4; nf++){
            const float* pb = Bs + (wnBase + nf*8 + g)*36 + kk + q;
            splitf(pb[0], bh[nf][0], bl[nf][0]);
            splitf(pb[4], bh[nf][1], bl[nf][1]);
        }
        #pragma unroll
        for (int nf = 0; nf < 4; nf++){
            mma_tf32(accH[nf], ah, bh[nf]);
            mma_tf32(accL[nf], ah, bl[nf]);
            mma_tf32(accL[nf], al, bh[nf]);
        }
    }
}

// ---------------- 1) pooled mean ---------------------------------------------
__global__ void __launch_bounds__(256) pool_kernel(const float* __restrict__ hid){
    int b = blockIdx.x;
    const float4* p = reinterpret_cast<const float4*>(hid + (size_t)b*S_*H_) + threadIdx.x;
    float ax=0.f,ay=0.f,az=0.f,aw=0.f;
    float bx=0.f,by=0.f,bz=0.f,bw=0.f;
    #pragma unroll 4
    for (int s=0; s<S_; s+=2){
        float4 v0 = p[(size_t)s*(H_/4)];
        float4 v1 = p[(size_t)(s+1)*(H_/4)];
        ax+=v0.x; ay+=v0.y; az+=v0.z; aw+=v0.w;
        bx+=v1.x; by+=v1.y; bz+=v1.z; bw+=v1.w;
    }
    float4 r;
    r.x=(ax+bx)*(1.f/S_); r.y=(ay+by)*(1.f/S_);
    r.z=(az+bz)*(1.f/S_); r.w=(aw+bw)*(1.f/S_);
    reinterpret_cast<float4*>(g_pooled + (size_t)b*H_)[threadIdx.x] = r;
}

// ---------------- 2) router + top-4 + softmax --------------------------------
__global__ void __launch_bounds__(512) router_topk_kernel(const float* __restrict__ hid,
                                                          const float* __restrict__ rW,
                                                          const float* __restrict__ rb){
    __shared__ float cls[H_];
    __shared__ float lg[E_];
    int b = blockIdx.x, tid = threadIdx.x;
    cls[tid]       = hid[(size_t)b*S_*H_ + tid];
    cls[tid + 512] = hid[(size_t)b*S_*H_ + tid + 512];
    __syncthreads();
    int w = tid >> 5, lane = tid & 31;
    float s = 0.f;
    const float* wr = rW + w*H_;
    #pragma unroll 8
    for (int j=lane; j<H_; j+=32) s += cls[j]*wr[j];
    #pragma unroll
    for (int o=16;o>0;o>>=1) s += __shfl_xor_sync(0xffffffffu, s, o);
    if (lane==0) lg[w] = s + rb[w];
    __syncthreads();
    if (tid==0){
        float v[E_];
        #pragma unroll
        for (int i=0;i<E_;i++) v[i]=lg[i];
        int   idxs[K_]; float vals[K_];
        for (int k=0;k<K_;k++){
            int bi=0; float bv=-3.0e38f;
            #pragma unroll
            for (int i=0;i<E_;i++){ if (v[i]>bv){ bv=v[i]; bi=i; } }
            idxs[k]=bi; vals[k]=bv; v[bi]=-3.0e38f;
        }
        float m = vals[0], ssum=0.f, wv[K_];
        for (int k=0;k<K_;k++){ wv[k]=expf(vals[k]-m); ssum+=wv[k]; }
        float inv = 1.f/ssum;
        for (int k=0;k<K_;k++){ g_topi[b*K_+k]=idxs[k]; g_topw[b*K_+k]=wv[k]*inv; }
    }
}

// ---------------- 3) gather (single block, smem counters) --------------------
__global__ void __launch_bounds__(1024) gather_kernel(){
    __shared__ int cnt[E_];
    int t = threadIdx.x;
    if (t < E_) cnt[t] = 0;
    __syncthreads();
    #pragma unroll
    for (int i=0;i<4;i++){
        int idx = t + i*1024;
        int e = g_topi[idx];
        int pos = atomicAdd(&cnt[e], 1);
        g_tok [e*B_+pos] = idx >> 2;
        g_slot[e*B_+pos] = idx & 3;
    }
    __syncthreads();
    if (t < E_) g_cnt[t] = cnt[t];
}

// ---------------- 4) dense head: t = tanh(cls @ dW^T + db) -------------------
__global__ void __launch_bounds__(128) dense_tanh_kernel(const float* __restrict__ hid,
                                                         const float* __restrict__ W,
                                                         const float* __restrict__ bias){
    __shared__ float As[2][64*36];
    __shared__ float Bs[2][64*36];
    int t = threadIdx.x, lane = t & 31, warp = t >> 5;
    int wm = warp >> 1, wn = warp & 1;
    int m0 = blockIdx.y*64, n0 = blockIdx.x*64;
    int lr = t >> 3, lc = (t & 7)*4;
    float accH[2][4][4], accL[2][4][4];
    #pragma unroll
    for (int i=0;i<2;i++)
        #pragma unroll
        for (int j=0;j<4;j++)
            #pragma unroll
            for (int k=0;k<4;k++){ accH[i][j][k]=0.f; accL[i][j][k]=0.f; }

    auto load = [&](int s, int k0){
        #pragma unroll
        for (int i=0;i<4;i++){
            int row = lr + 16*i;
            cp16(&As[s][row*36+lc], hid + (size_t)(m0+row)*S_*H_ + k0 + lc);
            cp16(&Bs[s][row*36+lc], W   + (size_t)(n0+row)*H_   + k0 + lc);
        }
    };
    load(0, 0); cp_commit();
    for (int it=0; it<32; it++){
        if (it+1 < 32){ load((it+1)&1, (it+1)*32); cp_commit(); cp_wait1(); }
        else cp_wait0();
        __syncthreads();
        compute_raw(As[it&1], Bs[it&1], wm*32, wn*32, lane, accH, accL);
        __syncthreads();
    }
    int g = lane>>2, q = lane&3;
    #pragma unroll
    for (int nf=0;nf<4;nf++){
        int col = n0 + wn*32 + nf*8 + 2*q;
        float2 bb = *(const float2*)&bias[col];
        #pragma unroll
        for (int mf=0;mf<2;mf++){
            int row = m0 + wm*32 + mf*16 + g;
            float2 o0, o1;
            o0.x = tanhf(accH[mf][nf][0]+accL[mf][nf][0]+bb.x);
            o0.y = tanhf(accH[mf][nf][1]+accL[mf][nf][1]+bb.y);
            o1.x = tanhf(accH[mf][nf][2]+accL[mf][nf][2]+bb.x);
            o1.y = tanhf(accH[mf][nf][3]+accL[mf][nf][3]+bb.y);
            *(float2*)&g_t[(size_t)row*H_ + col]     = o0;
            *(float2*)&g_t[(size_t)(row+8)*H_ + col] = o1;
        }
    }
}

// ---------------- 5) orig = t @ out_W^T + out_b ------------------------------
__global__ void __launch_bounds__(256) orig_kernel(const float* __restrict__ oW,
                                                   const float* __restrict__ ob){
    int w = threadIdx.x >> 5, lane = threadIdx.x & 31;
    int b = blockIdx.x*8 + w;
    const float* t = g_t + (size_t)b*H_;
    for (int c=0;c<C_;c++){
        float s=0.f;
        const float* wr = oW + c*H_;
        #pragma unroll 8
        for (int j=lane; j<H_; j+=32) s += t[j]*wr[j];
        #pragma unroll
        for (int o=16;o>0;o>>=1) s += __shfl_xor_sync(0xffffffffu, s, o);
        if (lane==0) g_orig[b*C_+c] = s + ob[c];
    }
}

// ---------------- 6) fused expert: GEMM1 + LN + GELU + GEMM2 + proj ----------
// 16 gathered rows x 256 cols per block; 256 threads (8 warps, warp 16x32).
__global__ void __launch_bounds__(256) expert_fused_kernel(const float* __restrict__ eW1,
                                                           const float* __restrict__ eb1,
                                                           const float* __restrict__ eg,
                                                           const float* __restrict__ ebt,
                                                           const float* __restrict__ eW2,
                                                           const float* __restrict__ eb2,
                                                           const float* __restrict__ pW,
                                                           const float* __restrict__ pb){
    extern __shared__ float sm[];
    float* As0 = sm;                    // 16*36
    float* As1 = sm + 576;
    float* Bs0 = sm + 1152;             // 256*36
    float* Bs1 = sm + 1152 + 9216;
    float* Cs  = sm + 19584;            // 16 x 260
    __shared__ int toks[16], slots[16];
    int e = blockIdx.y;
    int n = g_cnt[e];
    int r0 = blockIdx.x*16;
    if (r0 >= n) return;
    int t = threadIdx.x, lane = t & 31, warp = t >> 5;
    if (t < 16){
        int rc = min(r0 + t, n-1);
        toks[t]  = g_tok [e*B_+rc];
        slots[t] = g_slot[e*B_+rc];
    }
    __syncthreads();
    int lr = t >> 3, lc = (t & 7)*4;    // B rows lr+32i; A (t<128) row lr in 0..15
    float accH[4][4], accL[4][4];
    #pragma unroll
    for (int i=0;i<4;i++)
        #pragma unroll
        for (int j=0;j<4;j++){ accH[i][j]=0.f; accL[i][j]=0.f; }

    const float* w1 = eW1 + (size_t)e*HE_*H_;
    const float* arow = g_pooled + (size_t)toks[lr & 15]*H_ + lc;
    auto load1 = [&](float* Asb, float* Bsb, int k0){
        if (t < 128) cp16(&Asb[lr*36+lc], arow + k0);
        #pragma unroll
        for (int i=0;i<8;i++){
            int row = lr + 32*i;
            cp16(&Bsb[row*36+lc], w1 + (size_t)row*H_ + k0 + lc);
        }
    };
    // ---- phase 1 mainloop (K=1024, 32 iters, 2-stage) ----
    load1(As0, Bs0, 0); cp_commit();
    for (int it=0; it<32; it++){
        if (it+1 < 32){
            if ((it+1)&1) load1(As1, Bs1, (it+1)*32); else load1(As0, Bs0, (it+1)*32);
            cp_commit(); cp_wait1();
        } else cp_wait0();
        __syncthreads();
        if (it&1) compute16<36>(As1, Bs1, warp*32, lane, accH, accL);
        else      compute16<36>(As0, Bs0, warp*32, lane, accH, accL);
        __syncthreads();
    }
    // ---- stage C tile into Cs ----
    int g = lane>>2, q = lane&3;
    #pragma unroll
    for (int nf=0;nf<4;nf++){
        int col = warp*32 + nf*8 + 2*q;
        float2 a; a.x=accH[nf][0]+accL[nf][0]; a.y=accH[nf][1]+accL[nf][1];
        float2 b; b.x=accH[nf][2]+accL[nf][2]; b.y=accH[nf][3]+accL[nf][3];
        *(float2*)&Cs[g*260 + col]     = a;
        *(float2*)&Cs[(g+8)*260 + col] = b;
    }
    __syncthreads();
    // ---- prefetch first eW2 tile while doing LN ----
    const float* w2 = eW2 + (size_t)e*HE_*HE_;
    auto load2 = [&](float* Bsb, int k0){
        #pragma unroll
        for (int i=0;i<8;i++){
            int row = lr + 32*i;
            cp16(&Bsb[row*36+lc], w2 + (size_t)row*HE_ + k0 + lc);
        }
    };
    load2(Bs0, 0); cp_commit();
    // ---- LN + GELU in place: 16 threads per row, 16 cols each ----
    {
        int row = t >> 4, j = t & 15;
        const float* b1 = eb1 + e*HE_;
        float s = 0.f, qs = 0.f;
        #pragma unroll
        for (int cc=0; cc<16; cc+=4){
            float4 v = *(float4*)&Cs[row*260 + j*16 + cc];
            float4 bb = *(const float4*)&b1[j*16 + cc];
            v.x+=bb.x; v.y+=bb.y; v.z+=bb.z; v.w+=bb.w;
            s  += v.x+v.y+v.z+v.w;
            qs += v.x*v.x+v.y*v.y+v.z*v.z+v.w*v.w;
        }
        #pragma unroll
        for (int o=1;o<16;o<<=1){
            s  += __shfl_xor_sync(0xffffffffu, s,  o);
            qs += __shfl_xor_sync(0xffffffffu, qs, o);
        }
        float m = s*(1.f/HE_);
        float var = qs*(1.f/HE_) - m*m;
        float rstd = rsqrtf(var + 1e-5f);
        const float* gp = eg  + e*HE_;
        const float* bp = ebt + e*HE_;
        #pragma unroll
        for (int cc=0; cc<16; cc+=4){
            float4 v = *(float4*)&Cs[row*260 + j*16 + cc];
            float4 bb = *(const float4*)&b1[j*16 + cc];
            float4 gg = *(const float4*)&gp[j*16 + cc];
            float4 bt = *(const float4*)&bp[j*16 + cc];
            float z0 = (v.x+bb.x-m)*rstd*gg.x + bt.x;
            float z1 = (v.y+bb.y-m)*rstd*gg.y + bt.y;
            float z2 = (v.z+bb.z-m)*rstd*gg.z + bt.z;
            float z3 = (v.w+bb.w-m)*rstd*gg.w + bt.w;
            float4 o;
            o.x = 0.5f*z0*(1.f+erff(z0*0.70710678118654752f));
            o.y = 0.5f*z1*(1.f+erff(z1*0.70710678118654752f));
            o.z = 0.5f*z2*(1.f+erff(z2*0.70710678118654752f));
            o.w = 0.5f*z3*(1.f+erff(z3*0.70710678118654752f));
            *(float4*)&Cs[row*260 + j*16 + cc] = o;
        }
    }
    __syncthreads();
    // ---- phase 2 mainloop (K=256, 8 iters, 2-stage; A = Cs, stride 260) ----
    float acc2H[4][4], acc2L[4][4];
    #pragma unroll
    for (int i=0;i<4;i++)
        #pragma unroll
        for (int j=0;j<4;j++){ acc2H[i][j]=0.f; acc2L[i][j]=0.f; }
    for (int it=0; it<8; it++){
        if (it+1 < 8){
            if ((it+1)&1) load2(Bs1, (it+1)*32); else load2(Bs0, (it+1)*32);
            cp_commit(); cp_wait1();
        } else cp_wait0();
        __syncthreads();
        if (it&1) compute16<260>(Cs + it*32, Bs1, warp*32, lane, acc2H, acc2L);
        else      compute16<260>(Cs + it*32, Bs0, warp*32, lane, acc2H, acc2L);
        __syncthreads();
    }
    // ---- stage phase-2 C tile (overwrite Cs; loop ended with a sync) ----
    #pragma unroll
    for (int nf=0;nf<4;nf++){
        int col = warp*32 + nf*8 + 2*q;
        float2 a; a.x=acc2H[nf][0]+acc2L[nf][0]; a.y=acc2H[nf][1]+acc2L[nf][1];
        float2 b; b.x=acc2H[nf][2]+acc2L[nf][2]; b.y=acc2H[nf][3]+acc2L[nf][3];
        *(float2*)&Cs[g*260 + col]     = a;
        *(float2*)&Cs[(g+8)*260 + col] = b;
    }
    __syncthreads();
    // ---- proj epilogue: 16 threads/row, 16 cols each -> C=3 ----
    {
        int row = t >> 4, j = t & 15;
        int gr = r0 + row;
        const float* b2 = eb2 + e*HE_;
        float p0=0.f, p1=0.f, p2=0.f;
        #pragma unroll
        for (int cc=0; cc<16; cc+=4){
            float4 v = *(float4*)&Cs[row*260 + j*16 + cc];
            float4 bb = *(const float4*)&b2[j*16 + cc];
            v.x+=bb.x; v.y+=bb.y; v.z+=bb.z; v.w+=bb.w;
            float4 w0 = *(const float4*)&pW[0*HE_ + j*16 + cc];
            float4 w1p = *(const float4*)&pW[1*HE_ + j*16 + cc];
            float4 w2p = *(const float4*)&pW[2*HE_ + j*16 + cc];
            p0 += v.x*w0.x + v.y*w0.y + v.z*w0.z + v.w*w0.w;
            p1 += v.x*w1p.x + v.y*w1p.y + v.z*w1p.z + v.w*w1p.w;
            p2 += v.x*w2p.x + v.y*w2p.y + v.z*w2p.z + v.w*w2p.w;
        }
        #pragma unroll
        for (int o=1;o<16;o<<=1){
            p0 += __shfl_xor_sync(0xffffffffu, p0, o);
            p1 += __shfl_xor_sync(0xffffffffu, p1, o);
            p2 += __shfl_xor_sync(0xffffffffu, p2, o);
        }
        if (j == 0 && gr < n){
            int b = toks[row], sl = slots[row];
            float* o = &g_el[(b*K_+sl)*C_];
            o[0] = p0 + pb[0];
            o[1] = p1 + pb[1];
            o[2] = p2 + pb[2];
        }
    }
}

// ---------------- 8) final head ---------------------------------------------
__global__ void __launch_bounds__(256) final_kernel(const float* __restrict__ f1W,
                                                    const float* __restrict__ f1b,
                                                    const float* __restrict__ fg,
                                                    const float* __restrict__ fbt,
                                                    const float* __restrict__ f2W,
                                                    const float* __restrict__ f2b,
                                                    float* __restrict__ out){
    int b = blockIdx.x*blockDim.x + threadIdx.x;
    if (b >= B_) return;
    float comb[2*C_];
    #pragma unroll
    for (int c=0;c<C_;c++) comb[c] = g_orig[b*C_+c];
    float moe[C_]={0.f,0.f,0.f};
    #pragma unroll
    for (int k=0;k<K_;k++){
        float w = g_topw[b*K_+k];
        const float* el = &g_el[(b*K_+k)*C_];
        #pragma unroll
        for (int c=0;c<C_;c++) moe[c] += w*el[c];
    }
    #pragma unroll
    for (int c=0;c<C_;c++) comb[C_+c]=moe[c];
    float y[C_];
    #pragma unroll
    for (int c=0;c<C_;c++){
        float s = f1b[c];
        #pragma unroll
        for (int jj=0;jj<2*C_;jj++) s += comb[jj]*f1W[c*(2*C_)+jj];
        y[c]=s;
    }
    float m = (y[0]+y[1]+y[2])*(1.f/3.f);
    float d0=y[0]-m, d1=y[1]-m, d2=y[2]-m;
    float var = (d0*d0+d1*d1+d2*d2)*(1.f/3.f);
    float rs = rsqrtf(var + 1e-5f);
    float z[C_];
    #pragma unroll
    for (int c=0;c<C_;c++) z[c] = fmaxf(0.f, (y[c]-m)*rs*fg[c] + fbt[c]);
    #pragma unroll
    for (int c2=0;c2<C_;c2++){
        float s = f2b[c2];
        #pragma unroll
        for (int c=0;c<C_;c++) s += z[c]*f2W[c2*C_+c];
        out[b*C_+c2] = s;
    }
}

// ---------------- streams/events (host-side objects, created once) -----------
struct SideStreams {
    cudaStream_t sB, sC;
    cudaEvent_t  evFork, evJB, evJC;
    SideStreams(){
        cudaStreamCreateWithFlags(&sB, cudaStreamNonBlocking);
        cudaStreamCreateWithFlags(&sC, cudaStreamNonBlocking);
        cudaEventCreateWithFlags(&evFork, cudaEventDisableTiming);
        cudaEventCreateWithFlags(&evJB,   cudaEventDisableTiming);
        cudaEventCreateWithFlags(&evJC,   cudaEventDisableTiming);
    }
};
static SideStreams g_ss;

// ---------------- launch -----------------------------------------------------
extern "C" void kernel_launch(void* const* d_in, const int* in_sizes, int n_in,
                              void* d_out, int out_size){
    const float* hid = (const float*)d_in[0];
    const float* rW  = (const float*)d_in[1];
    const float* rb  = (const float*)d_in[2];
    const float* eW1 = (const float*)d_in[3];
    const float* eb1 = (const float*)d_in[4];
    const float* eg  = (const float*)d_in[5];
    const float* ebt = (const float*)d_in[6];
    const float* eW2 = (const float*)d_in[7];
    const float* eb2 = (const float*)d_in[8];
    const float* pW  = (const float*)d_in[9];
    const float* pb  = (const float*)d_in[10];
    const float* dW  = (const float*)d_in[11];
    const float* db  = (const float*)d_in[12];
    const float* oW  = (const float*)d_in[13];
    const float* ob  = (const float*)d_in[14];
    const float* f1W = (const float*)d_in[15];
    const float* f1b = (const float*)d_in[16];
    const float* fg  = (const float*)d_in[17];
    const float* fbt = (const float*)d_in[18];
    const float* f2W = (const float*)d_in[19];
    const float* f2b = (const float*)d_in[20];
    float* out = (float*)d_out;

    const int DSM_EXP = (2*16*36 + 2*256*36 + 16*260)*4;  // 94976 B
    cudaFuncSetAttribute(expert_fused_kernel, cudaFuncAttributeMaxDynamicSharedMemorySize, DSM_EXP);

    // fork branches
    cudaEventRecord(g_ss.evFork, 0);
    cudaStreamWaitEvent(g_ss.sB, g_ss.evFork, 0);
    cudaStreamWaitEvent(g_ss.sC, g_ss.evFork, 0);

    // main stream: HBM-bound pool (critical path)
    pool_kernel<<<B_, 256>>>(hid);

    // branch B: router + gather
    router_topk_kernel<<<B_, 512, 0, g_ss.sB>>>(hid, rW, rb);
    gather_kernel<<<1, 1024, 0, g_ss.sB>>>();
    cudaEventRecord(g_ss.evJB, g_ss.sB);

    // branch C: dense head + orig
    dense_tanh_kernel<<<dim3(16,16), 128, 0, g_ss.sC>>>(hid, dW, db);
    orig_kernel<<<B_/8, 256, 0, g_ss.sC>>>(oW, ob);
    cudaEventRecord(g_ss.evJC, g_ss.sC);

    // join B before fused expert kernel
    cudaStreamWaitEvent(0, g_ss.evJB, 0);
    expert_fused_kernel<<<dim3(B_/16, E_), 256, DSM_EXP>>>(eW1, eb1, eg, ebt,
                                                           eW2, eb2, pW, pb);

    // join C before final head
    cudaStreamWaitEvent(0, g_ss.evJC, 0);
    final_kernel<<<B_/256, 256>>>(f1W, f1b, fg, fbt, f2W, f2b, out);
}

// round 12
// speedup vs baseline: 1.1481x; 1.1037x over previous
#include <cuda_runtime.h>
#include <math.h>
#include <stdint.h>

#define B_  1024
#define S_  256
#define H_  1024
#define E_  16
#define K_  4
#define HE_ 256
#define C_  3
#define HB_ 512   // half batch

// ---------------- device scratch ---------------------------------------------
__device__ float g_pooled[B_*H_];
__device__ float g_t[B_*H_];
__device__ float g_orig[B_*C_];
__device__ int   g_topi[B_*K_];
__device__ float g_topw[B_*K_];
__device__ int   g_cnt[2*E_];
__device__ int   g_tok[2*E_*HB_];
__device__ int   g_slot[2*E_*HB_];
__device__ float g_el[B_*K_*C_];

// ---------------- cp.async helpers -------------------------------------------
__device__ __forceinline__ void cp16(void* dst, const void* src){
    unsigned d = (unsigned)__cvta_generic_to_shared(dst);
    asm volatile("cp.async.cg.shared.global [%0], [%1], 16;\n" :: "r"(d), "l"(src));
}
__device__ __forceinline__ void cp_commit(){ asm volatile("cp.async.commit_group;\n" ::); }
__device__ __forceinline__ void cp_wait1(){ asm volatile("cp.async.wait_group 1;\n" ::); }
__device__ __forceinline__ void cp_wait0(){ asm volatile("cp.async.wait_group 0;\n" ::); }

// ---------------- tf32 mma + in-register split -------------------------------
__device__ __forceinline__ void mma_tf32(float* c, const unsigned* a, const unsigned* b){
    asm volatile("mma.sync.aligned.m16n8k8.row.col.f32.tf32.tf32.f32 "
        "{%0,%1,%2,%3},{%4,%5,%6,%7},{%8,%9},{%0,%1,%2,%3};\n"
        : "+f"(c[0]), "+f"(c[1]), "+f"(c[2]), "+f"(c[3])
        : "r"(a[0]), "r"(a[1]), "r"(a[2]), "r"(a[3]), "r"(b[0]), "r"(b[1]));
}

__device__ __forceinline__ void splitf(float a, unsigned& hi, unsigned& lo){
    unsigned u = __float_as_uint(a) & 0xffffe000u;
    hi = u;
    lo = __float_as_uint(a - __uint_as_float(u));
}

// warp tile 32(m) x 32(n), BK=32, raw fp32 smem tiles (stride 36), 3xTF32, ILP-split.
__device__ __forceinline__ void compute_raw(const float* __restrict__ As,
                                            const float* __restrict__ Bs,
                                            int wmBase, int wnBase, int lane,
                                            float (&accH)[2][4][4],
                                            float (&accL)[2][4][4]){
    int g = lane >> 2, q = lane & 3;
    #pragma unroll
    for (int kk = 0; kk < 32; kk += 8){
        unsigned ah[2][4], al[2][4], bh[4][2], bl[4][2];
        #pragma unroll
        for (int mf = 0; mf < 2; mf++){
            int r = wmBase + mf*16 + g;
            const float* p = As + r*36 + kk + q;
            splitf(p[0],      ah[mf][0], al[mf][0]);
            splitf(p[8*36],   ah[mf][1], al[mf][1]);
            splitf(p[4],      ah[mf][2], al[mf][2]);
            splitf(p[8*36+4], ah[mf][3], al[mf][3]);
        }
        #pragma unroll
        for (int nf = 0; nf < 4; nf++){
            int nn = wnBase + nf*8 + g;
            const float* p = Bs + nn*36 + kk + q;
            splitf(p[0], bh[nf][0], bl[nf][0]);
            splitf(p[4], bh[nf][1], bl[nf][1]);
        }
        #pragma unroll
        for (int mf = 0; mf < 2; mf++)
            #pragma unroll
            for (int nf = 0; nf < 4; nf++){
                mma_tf32(accH[mf][nf], ah[mf], bh[nf]);
                mma_tf32(accL[mf][nf], ah[mf], bl[nf]);
                mma_tf32(accL[mf][nf], al[mf], bh[nf]);
            }
    }
}

// warp tile 16(m) x 32(n); A stride templated (36 staged, 260 for Cs). ILP-split.
template<int AS>
__device__ __forceinline__ void compute16(const float* __restrict__ Asl,
                                          const float* __restrict__ Bs,
                                          int wnBase, int lane,
                                          float (&accH)[4][4], float (&accL)[4][4]){
    int g = lane >> 2, q = lane & 3;
    #pragma unroll
    for (int kk = 0; kk < 32; kk += 8){
        unsigned ah[4], al[4], bh[4][2], bl[4][2];
        const float* p = Asl + g*AS + kk + q;
        splitf(p[0],      ah[0], al[0]);
        splitf(p[8*AS],   ah[1], al[1]);
        splitf(p[4],      ah[2], al[2]);
        splitf(p[8*AS+4], ah[3], al[3]);
        #pragma unroll
        for (int nf = 0; nf < 4; nf++){
            const float* pb = Bs + (wnBase + nf*8 + g)*36 + kk + q;
            splitf(pb[0], bh[nf][0], bl[nf][0]);
            splitf(pb[4], bh[nf][1], bl[nf][1]);
        }
        #pragma unroll
        for (int nf = 0; nf < 4; nf++){
            mma_tf32(accH[nf], ah, bh[nf]);
            mma_tf32(accL[nf], ah, bl[nf]);
            mma_tf32(accL[nf], al, bh[nf]);
        }
    }
}

// ---------------- 1) pooled mean (half batch per launch) ---------------------
__global__ void __launch_bounds__(256) pool_kernel(const float* __restrict__ hid, int base){
    int b = base + blockIdx.x;
    const float4* p = reinterpret_cast<const float4*>(hid + (size_t)b*S_*H_) + threadIdx.x;
    float ax=0.f,ay=0.f,az=0.f,aw=0.f;
    float bx=0.f,by=0.f,bz=0.f,bw=0.f;
    #pragma unroll 4
    for (int s=0; s<S_; s+=2){
        float4 v0 = p[(size_t)s*(H_/4)];
        float4 v1 = p[(size_t)(s+1)*(H_/4)];
        ax+=v0.x; ay+=v0.y; az+=v0.z; aw+=v0.w;
        bx+=v1.x; by+=v1.y; bz+=v1.z; bw+=v1.w;
    }
    float4 r;
    r.x=(ax+bx)*(1.f/S_); r.y=(ay+by)*(1.f/S_);
    r.z=(az+bz)*(1.f/S_); r.w=(aw+bw)*(1.f/S_);
    reinterpret_cast<float4*>(g_pooled + (size_t)b*H_)[threadIdx.x] = r;
}

// ---------------- 2) router + top-4 + softmax --------------------------------
__global__ void __launch_bounds__(512) router_topk_kernel(const float* __restrict__ hid,
                                                          const float* __restrict__ rW,
                                                          const float* __restrict__ rb){
    __shared__ float cls[H_];
    __shared__ float lg[E_];
    int b = blockIdx.x, tid = threadIdx.x;
    cls[tid]       = hid[(size_t)b*S_*H_ + tid];
    cls[tid + 512] = hid[(size_t)b*S_*H_ + tid + 512];
    __syncthreads();
    int w = tid >> 5, lane = tid & 31;
    float s = 0.f;
    const float* wr = rW + w*H_;
    #pragma unroll 8
    for (int j=lane; j<H_; j+=32) s += cls[j]*wr[j];
    #pragma unroll
    for (int o=16;o>0;o>>=1) s += __shfl_xor_sync(0xffffffffu, s, o);
    if (lane==0) lg[w] = s + rb[w];
    __syncthreads();
    if (tid==0){
        float v[E_];
        #pragma unroll
        for (int i=0;i<E_;i++) v[i]=lg[i];
        int   idxs[K_]; float vals[K_];
        for (int k=0;k<K_;k++){
            int bi=0; float bv=-3.0e38f;
            #pragma unroll
            for (int i=0;i<E_;i++){ if (v[i]>bv){ bv=v[i]; bi=i; } }
            idxs[k]=bi; vals[k]=bv; v[bi]=-3.0e38f;
        }
        float m = vals[0], ssum=0.f, wv[K_];
        for (int k=0;k<K_;k++){ wv[k]=expf(vals[k]-m); ssum+=wv[k]; }
        float inv = 1.f/ssum;
        for (int k=0;k<K_;k++){ g_topi[b*K_+k]=idxs[k]; g_topw[b*K_+k]=wv[k]*inv; }
    }
}

// ---------------- 3) gather per half (single block, smem counters) -----------
__global__ void __launch_bounds__(1024) gather_kernel(int half){
    __shared__ int cnt[E_];
    int t = threadIdx.x;
    if (t < E_) cnt[t] = 0;
    __syncthreads();
    int base = half*HB_*K_;
    #pragma unroll
    for (int i=0;i<2;i++){
        int idx = base + t + i*1024;
        int e = g_topi[idx];
        int pos = atomicAdd(&cnt[e], 1);
        g_tok [(half*E_+e)*HB_+pos] = idx >> 2;
        g_slot[(half*E_+e)*HB_+pos] = idx & 3;
    }
    __syncthreads();
    if (t < E_) g_cnt[half*E_+t] = cnt[t];
}

// ---------------- 4) dense head: t = tanh(cls @ dW^T + db) -------------------
__global__ void __launch_bounds__(128) dense_tanh_kernel(const float* __restrict__ hid,
                                                         const float* __restrict__ W,
                                                         const float* __restrict__ bias){
    __shared__ float As[2][64*36];
    __shared__ float Bs[2][64*36];
    int t = threadIdx.x, lane = t & 31, warp = t >> 5;
    int wm = warp >> 1, wn = warp & 1;
    int m0 = blockIdx.y*64, n0 = blockIdx.x*64;
    int lr = t >> 3, lc = (t & 7)*4;
    float accH[2][4][4], accL[2][4][4];
    #pragma unroll
    for (int i=0;i<2;i++)
        #pragma unroll
        for (int j=0;j<4;j++)
            #pragma unroll
            for (int k=0;k<4;k++){ accH[i][j][k]=0.f; accL[i][j][k]=0.f; }

    auto load = [&](int s, int k0){
        #pragma unroll
        for (int i=0;i<4;i++){
            int row = lr + 16*i;
            cp16(&As[s][row*36+lc], hid + (size_t)(m0+row)*S_*H_ + k0 + lc);
            cp16(&Bs[s][row*36+lc], W   + (size_t)(n0+row)*H_   + k0 + lc);
        }
    };
    load(0, 0); cp_commit();
    for (int it=0; it<32; it++){
        if (it+1 < 32){ load((it+1)&1, (it+1)*32); cp_commit(); cp_wait1(); }
        else cp_wait0();
        __syncthreads();
        compute_raw(As[it&1], Bs[it&1], wm*32, wn*32, lane, accH, accL);
        __syncthreads();
    }
    int g = lane>>2, q = lane&3;
    #pragma unroll
    for (int nf=0;nf<4;nf++){
        int col = n0 + wn*32 + nf*8 + 2*q;
        float2 bb = *(const float2*)&bias[col];
        #pragma unroll
        for (int mf=0;mf<2;mf++){
            int row = m0 + wm*32 + mf*16 + g;
            float2 o0, o1;
            o0.x = tanhf(accH[mf][nf][0]+accL[mf][nf][0]+bb.x);
            o0.y = tanhf(accH[mf][nf][1]+accL[mf][nf][1]+bb.y);
            o1.x = tanhf(accH[mf][nf][2]+accL[mf][nf][2]+bb.x);
            o1.y = tanhf(accH[mf][nf][3]+accL[mf][nf][3]+bb.y);
            *(float2*)&g_t[(size_t)row*H_ + col]     = o0;
            *(float2*)&g_t[(size_t)(row+8)*H_ + col] = o1;
        }
    }
}

// ---------------- 5) orig = t @ out_W^T + out_b ------------------------------
__global__ void __launch_bounds__(256) orig_kernel(const float* __restrict__ oW,
                                                   const float* __restrict__ ob){
    int w = threadIdx.x >> 5, lane = threadIdx.x & 31;
    int b = blockIdx.x*8 + w;
    const float* t = g_t + (size_t)b*H_;
    for (int c=0;c<C_;c++){
        float s=0.f;
        const float* wr = oW + c*H_;
        #pragma unroll 8
        for (int j=lane; j<H_; j+=32) s += t[j]*wr[j];
        #pragma unroll
        for (int o=16;o>0;o>>=1) s += __shfl_xor_sync(0xffffffffu, s, o);
        if (lane==0) g_orig[b*C_+c] = s + ob[c];
    }
}

// ---------------- 6) fused expert (per half): GEMM1+LN+GELU+GEMM2+proj -------
// 16 gathered rows x 256 cols per block; 256 threads (8 warps, warp 16x32).
__global__ void __launch_bounds__(256) expert_fused_kernel(const float* __restrict__ eW1,
                                                           const float* __restrict__ eb1,
                                                           const float* __restrict__ eg,
                                                           const float* __restrict__ ebt,
                                                           const float* __restrict__ eW2,
                                                           const float* __restrict__ eb2,
                                                           const float* __restrict__ pW,
                                                           const float* __restrict__ pb,
                                                           int half){
    extern __shared__ float sm[];
    float* As0 = sm;                    // 16*36
    float* As1 = sm + 576;
    float* Bs0 = sm + 1152;             // 256*36
    float* Bs1 = sm + 1152 + 9216;
    float* Cs  = sm + 19584;            // 16 x 260
    __shared__ int toks[16], slots[16];
    int e = blockIdx.y;
    int n = g_cnt[half*E_+e];
    int r0 = blockIdx.x*16;
    if (r0 >= n) return;
    const int* tokb  = g_tok  + (half*E_+e)*HB_;
    const int* slotb = g_slot + (half*E_+e)*HB_;
    int t = threadIdx.x, lane = t & 31, warp = t >> 5;
    if (t < 16){
        int rc = min(r0 + t, n-1);
        toks[t]  = tokb [rc];
        slots[t] = slotb[rc];
    }
    __syncthreads();
    int lr = t >> 3, lc = (t & 7)*4;
    float accH[4][4], accL[4][4];
    #pragma unroll
    for (int i=0;i<4;i++)
        #pragma unroll
        for (int j=0;j<4;j++){ accH[i][j]=0.f; accL[i][j]=0.f; }

    const float* w1 = eW1 + (size_t)e*HE_*H_;
    const float* arow = g_pooled + (size_t)toks[lr & 15]*H_ + lc;
    auto load1 = [&](float* Asb, float* Bsb, int k0){
        if (t < 128) cp16(&Asb[lr*36+lc], arow + k0);
        #pragma unroll
        for (int i=0;i<8;i++){
            int row = lr + 32*i;
            cp16(&Bsb[row*36+lc], w1 + (size_t)row*H_ + k0 + lc);
        }
    };
    // ---- phase 1 mainloop (K=1024, 32 iters, 2-stage) ----
    load1(As0, Bs0, 0); cp_commit();
    for (int it=0; it<32; it++){
        if (it+1 < 32){
            if ((it+1)&1) load1(As1, Bs1, (it+1)*32); else load1(As0, Bs0, (it+1)*32);
            cp_commit(); cp_wait1();
        } else cp_wait0();
        __syncthreads();
        if (it&1) compute16<36>(As1, Bs1, warp*32, lane, accH, accL);
        else      compute16<36>(As0, Bs0, warp*32, lane, accH, accL);
        __syncthreads();
    }
    // ---- stage C tile into Cs ----
    int g = lane>>2, q = lane&3;
    #pragma unroll
    for (int nf=0;nf<4;nf++){
        int col = warp*32 + nf*8 + 2*q;
        float2 a; a.x=accH[nf][0]+accL[nf][0]; a.y=accH[nf][1]+accL[nf][1];
        float2 b; b.x=accH[nf][2]+accL[nf][2]; b.y=accH[nf][3]+accL[nf][3];
        *(float2*)&Cs[g*260 + col]     = a;
        *(float2*)&Cs[(g+8)*260 + col] = b;
    }
    __syncthreads();
    // ---- prefetch first eW2 tile while doing LN ----
    const float* w2 = eW2 + (size_t)e*HE_*HE_;
    auto load2 = [&](float* Bsb, int k0){
        #pragma unroll
        for (int i=0;i<8;i++){
            int row = lr + 32*i;
            cp16(&Bsb[row*36+lc], w2 + (size_t)row*HE_ + k0 + lc);
        }
    };
    load2(Bs0, 0); cp_commit();
    // ---- LN + GELU in place: 16 threads per row, 16 cols each ----
    {
        int row = t >> 4, j = t & 15;
        const float* b1 = eb1 + e*HE_;
        float s = 0.f, qs = 0.f;
        #pragma unroll
        for (int cc=0; cc<16; cc+=4){
            float4 v = *(float4*)&Cs[row*260 + j*16 + cc];
            float4 bb = *(const float4*)&b1[j*16 + cc];
            v.x+=bb.x; v.y+=bb.y; v.z+=bb.z; v.w+=bb.w;
            s  += v.x+v.y+v.z+v.w;
            qs += v.x*v.x+v.y*v.y+v.z*v.z+v.w*v.w;
        }
        #pragma unroll
        for (int o=1;o<16;o<<=1){
            s  += __shfl_xor_sync(0xffffffffu, s,  o);
            qs += __shfl_xor_sync(0xffffffffu, qs, o);
        }
        float m = s*(1.f/HE_);
        float var = qs*(1.f/HE_) - m*m;
        float rstd = rsqrtf(var + 1e-5f);
        const float* gp = eg  + e*HE_;
        const float* bp = ebt + e*HE_;
        #pragma unroll
        for (int cc=0; cc<16; cc+=4){
            float4 v = *(float4*)&Cs[row*260 + j*16 + cc];
            float4 bb = *(const float4*)&b1[j*16 + cc];
            float4 gg = *(const float4*)&gp[j*16 + cc];
            float4 bt = *(const float4*)&bp[j*16 + cc];
            float z0 = (v.x+bb.x-m)*rstd*gg.x + bt.x;
            float z1 = (v.y+bb.y-m)*rstd*gg.y + bt.y;
            float z2 = (v.z+bb.z-m)*rstd*gg.z + bt.z;
            float z3 = (v.w+bb.w-m)*rstd*gg.w + bt.w;
            float4 o;
            o.x = 0.5f*z0*(1.f+erff(z0*0.70710678118654752f));
            o.y = 0.5f*z1*(1.f+erff(z1*0.70710678118654752f));
            o.z = 0.5f*z2*(1.f+erff(z2*0.70710678118654752f));
            o.w = 0.5f*z3*(1.f+erff(z3*0.70710678118654752f));
            *(float4*)&Cs[row*260 + j*16 + cc] = o;
        }
    }
    __syncthreads();
    // ---- phase 2 mainloop (K=256, 8 iters, 2-stage; A = Cs, stride 260) ----
    float acc2H[4][4], acc2L[4][4];
    #pragma unroll
    for (int i=0;i<4;i++)
        #pragma unroll
        for (int j=0;j<4;j++){ acc2H[i][j]=0.f; acc2L[i][j]=0.f; }
    for (int it=0; it<8; it++){
        if (it+1 < 8){
            if ((it+1)&1) load2(Bs1, (it+1)*32); else load2(Bs0, (it+1)*32);
            cp_commit(); cp_wait1();
        } else cp_wait0();
        __syncthreads();
        if (it&1) compute16<260>(Cs + it*32, Bs1, warp*32, lane, acc2H, acc2L);
        else      compute16<260>(Cs + it*32, Bs0, warp*32, lane, acc2H, acc2L);
        __syncthreads();
    }
    // ---- stage phase-2 C tile (overwrite Cs) ----
    #pragma unroll
    for (int nf=0;nf<4;nf++){
        int col = warp*32 + nf*8 + 2*q;
        float2 a; a.x=acc2H[nf][0]+acc2L[nf][0]; a.y=acc2H[nf][1]+acc2L[nf][1];
        float2 b; b.x=acc2H[nf][2]+acc2L[nf][2]; b.y=acc2H[nf][3]+acc2L[nf][3];
        *(float2*)&Cs[g*260 + col]     = a;
        *(float2*)&Cs[(g+8)*260 + col] = b;
    }
    __syncthreads();
    // ---- proj epilogue: 16 threads/row, 16 cols each -> C=3 ----
    {
        int row = t >> 4, j = t & 15;
        int gr = r0 + row;
        const float* b2 = eb2 + e*HE_;
        float p0=0.f, p1=0.f, p2=0.f;
        #pragma unroll
        for (int cc=0; cc<16; cc+=4){
            float4 v = *(float4*)&Cs[row*260 + j*16 + cc];
            float4 bb = *(const float4*)&b2[j*16 + cc];
            v.x+=bb.x; v.y+=bb.y; v.z+=bb.z; v.w+=bb.w;
            float4 w0 = *(const float4*)&pW[0*HE_ + j*16 + cc];
            float4 w1p = *(const float4*)&pW[1*HE_ + j*16 + cc];
            float4 w2p = *(const float4*)&pW[2*HE_ + j*16 + cc];
            p0 += v.x*w0.x + v.y*w0.y + v.z*w0.z + v.w*w0.w;
            p1 += v.x*w1p.x + v.y*w1p.y + v.z*w1p.z + v.w*w1p.w;
            p2 += v.x*w2p.x + v.y*w2p.y + v.z*w2p.z + v.w*w2p.w;
        }
        #pragma unroll
        for (int o=1;o<16;o<<=1){
            p0 += __shfl_xor_sync(0xffffffffu, p0, o);
            p1 += __shfl_xor_sync(0xffffffffu, p1, o);
            p2 += __shfl_xor_sync(0xffffffffu, p2, o);
        }
        if (j == 0 && gr < n){
            int b = toks[row], sl = slots[row];
            float* o = &g_el[(b*K_+sl)*C_];
            o[0] = p0 + pb[0];
            o[1] = p1 + pb[1];
            o[2] = p2 + pb[2];
        }
    }
}

// ---------------- 8) final head ---------------------------------------------
__global__ void __launch_bounds__(256) final_kernel(const float* __restrict__ f1W,
                                                    const float* __restrict__ f1b,
                                                    const float* __restrict__ fg,
                                                    const float* __restrict__ fbt,
                                                    const float* __restrict__ f2W,
                                                    const float* __restrict__ f2b,
                                                    float* __restrict__ out){
    int b = blockIdx.x*blockDim.x + threadIdx.x;
    if (b >= B_) return;
    float comb[2*C_];
    #pragma unroll
    for (int c=0;c<C_;c++) comb[c] = g_orig[b*C_+c];
    float moe[C_]={0.f,0.f,0.f};
    #pragma unroll
    for (int k=0;k<K_;k++){
        float w = g_topw[b*K_+k];
        const float* el = &g_el[(b*K_+k)*C_];
        #pragma unroll
        for (int c=0;c<C_;c++) moe[c] += w*el[c];
    }
    #pragma unroll
    for (int c=0;c<C_;c++) comb[C_+c]=moe[c];
    float y[C_];
    #pragma unroll
    for (int c=0;c<C_;c++){
        float s = f1b[c];
        #pragma unroll
        for (int jj=0;jj<2*C_;jj++) s += comb[jj]*f1W[c*(2*C_)+jj];
        y[c]=s;
    }
    float m = (y[0]+y[1]+y[2])*(1.f/3.f);
    float d0=y[0]-m, d1=y[1]-m, d2=y[2]-m;
    float var = (d0*d0+d1*d1+d2*d2)*(1.f/3.f);
    float rs = rsqrtf(var + 1e-5f);
    float z[C_];
    #pragma unroll
    for (int c=0;c<C_;c++) z[c] = fmaxf(0.f, (y[c]-m)*rs*fg[c] + fbt[c]);
    #pragma unroll
    for (int c2=0;c2<C_;c2++){
        float s = f2b[c2];
        #pragma unroll
        for (int c=0;c<C_;c++) s += z[c]*f2W[c2*C_+c];
        out[b*C_+c2] = s;
    }
}

// ---------------- streams/events (host-side objects, created once) -----------
struct SideStreams {
    cudaStream_t sB, sC, sE;
    cudaEvent_t  evFork, evJC, evG0, evG1, evP0, evE0;
    SideStreams(){
        cudaStreamCreateWithFlags(&sB, cudaStreamNonBlocking);
        cudaStreamCreateWithFlags(&sC, cudaStreamNonBlocking);
        cudaStreamCreateWithFlags(&sE, cudaStreamNonBlocking);
        cudaEventCreateWithFlags(&evFork, cudaEventDisableTiming);
        cudaEventCreateWithFlags(&evJC,   cudaEventDisableTiming);
        cudaEventCreateWithFlags(&evG0,   cudaEventDisableTiming);
        cudaEventCreateWithFlags(&evG1,   cudaEventDisableTiming);
        cudaEventCreateWithFlags(&evP0,   cudaEventDisableTiming);
        cudaEventCreateWithFlags(&evE0,   cudaEventDisableTiming);
    }
};
static SideStreams g_ss;

// ---------------- launch -----------------------------------------------------
extern "C" void kernel_launch(void* const* d_in, const int* in_sizes, int n_in,
                              void* d_out, int out_size){
    const float* hid = (const float*)d_in[0];
    const float* rW  = (const float*)d_in[1];
    const float* rb  = (const float*)d_in[2];
    const float* eW1 = (const float*)d_in[3];
    const float* eb1 = (const float*)d_in[4];
    const float* eg  = (const float*)d_in[5];
    const float* ebt = (const float*)d_in[6];
    const float* eW2 = (const float*)d_in[7];
    const float* eb2 = (const float*)d_in[8];
    const float* pW  = (const float*)d_in[9];
    const float* pb  = (const float*)d_in[10];
    const float* dW  = (const float*)d_in[11];
    const float* db  = (const float*)d_in[12];
    const float* oW  = (const float*)d_in[13];
    const float* ob  = (const float*)d_in[14];
    const float* f1W = (const float*)d_in[15];
    const float* f1b = (const float*)d_in[16];
    const float* fg  = (const float*)d_in[17];
    const float* fbt = (const float*)d_in[18];
    const float* f2W = (const float*)d_in[19];
    const float* f2b = (const float*)d_in[20];
    float* out = (float*)d_out;

    const int DSM_EXP = (2*16*36 + 2*256*36 + 16*260)*4;  // 94976 B
    cudaFuncSetAttribute(expert_fused_kernel, cudaFuncAttributeMaxDynamicSharedMemorySize, DSM_EXP);

    // fork branches
    cudaEventRecord(g_ss.evFork, 0);
    cudaStreamWaitEvent(g_ss.sB, g_ss.evFork, 0);
    cudaStreamWaitEvent(g_ss.sC, g_ss.evFork, 0);

    // main stream: pool half 0, then half 1 (HBM-bound critical path)
    pool_kernel<<<HB_, 256>>>(hid, 0);
    cudaEventRecord(g_ss.evP0, 0);
    pool_kernel<<<HB_, 256>>>(hid, HB_);

    // branch B: router (all tokens; cls only) + per-half gathers
    router_topk_kernel<<<B_, 512, 0, g_ss.sB>>>(hid, rW, rb);
    gather_kernel<<<1, 1024, 0, g_ss.sB>>>(0);
    cudaEventRecord(g_ss.evG0, g_ss.sB);
    gather_kernel<<<1, 1024, 0, g_ss.sB>>>(1);
    cudaEventRecord(g_ss.evG1, g_ss.sB);

    // branch C: dense head + orig
    dense_tanh_kernel<<<dim3(16,16), 128, 0, g_ss.sC>>>(hid, dW, db);
    orig_kernel<<<B_/8, 256, 0, g_ss.sC>>>(oW, ob);
    cudaEventRecord(g_ss.evJC, g_ss.sC);

    // stream E: expert half 0 overlapped with pool half 1
    cudaStreamWaitEvent(g_ss.sE, g_ss.evP0, 0);
    cudaStreamWaitEvent(g_ss.sE, g_ss.evG0, 0);
    expert_fused_kernel<<<dim3(HB_/16, E_), 256, DSM_EXP, g_ss.sE>>>(
        eW1, eb1, eg, ebt, eW2, eb2, pW, pb, 0);
    cudaEventRecord(g_ss.evE0, g_ss.sE);

    // main: expert half 1 after pool half 1 (+gather 1)
    cudaStreamWaitEvent(0, g_ss.evG1, 0);
    expert_fused_kernel<<<dim3(HB_/16, E_), 256, DSM_EXP>>>(
        eW1, eb1, eg, ebt, eW2, eb2, pW, pb, 1);

    // final: needs expert half 0 (stream E), orig (stream C), expert half 1 (main)
    cudaStreamWaitEvent(0, g_ss.evE0, 0);
    cudaStreamWaitEvent(0, g_ss.evJC, 0);
    final_kernel<<<B_/256, 256>>>(f1W, f1b, fg, fbt, f2W, f2b, out);
}

// round 14
// speedup vs baseline: 1.1502x; 1.0018x over previous
#include <cuda_runtime.h>
#include <math.h>
#include <stdint.h>

#define B_  1024
#define S_  256
#define H_  1024
#define E_  16
#define K_  4
#define HE_ 256
#define C_  3
#define H0_ 640   // first split (overlapped with pool of second split)
#define H1_ 384   // second split (exposed tail)

// ---------------- device scratch ---------------------------------------------
__device__ float g_pooled[B_*H_];
__device__ float g_t[B_*H_];
__device__ float g_orig[B_*C_];
__device__ int   g_topi[B_*K_];
__device__ float g_topw[B_*K_];
__device__ int   g_cnt[2*E_];
__device__ int   g_tok[2*E_*B_];
__device__ int   g_slot[2*E_*B_];
__device__ float g_el[B_*K_*C_];

// ---------------- cp.async helpers -------------------------------------------
__device__ __forceinline__ void cp16(void* dst, const void* src){
    unsigned d = (unsigned)__cvta_generic_to_shared(dst);
    asm volatile("cp.async.cg.shared.global [%0], [%1], 16;\n" :: "r"(d), "l"(src));
}
__device__ __forceinline__ void cp_commit(){ asm volatile("cp.async.commit_group;\n" ::); }
__device__ __forceinline__ void cp_wait1(){ asm volatile("cp.async.wait_group 1;\n" ::); }
__device__ __forceinline__ void cp_wait0(){ asm volatile("cp.async.wait_group 0;\n" ::); }

// ---------------- tf32 mma + in-register split -------------------------------
__device__ __forceinline__ void mma_tf32(float* c, const unsigned* a, const unsigned* b){
    asm volatile("mma.sync.aligned.m16n8k8.row.col.f32.tf32.tf32.f32 "
        "{%0,%1,%2,%3},{%4,%5,%6,%7},{%8,%9},{%0,%1,%2,%3};\n"
        : "+f"(c[0]), "+f"(c[1]), "+f"(c[2]), "+f"(c[3])
        : "r"(a[0]), "r"(a[1]), "r"(a[2]), "r"(a[3]), "r"(b[0]), "r"(b[1]));
}

__device__ __forceinline__ void splitf(float a, unsigned& hi, unsigned& lo){
    unsigned u = __float_as_uint(a) & 0xffffe000u;
    hi = u;
    lo = __float_as_uint(a - __uint_as_float(u));
}

// warp tile 32(m) x 32(n), BK=32, raw fp32 smem tiles (stride 36), 3xTF32, ILP-split.
__device__ __forceinline__ void compute_raw(const float* __restrict__ As,
                                            const float* __restrict__ Bs,
                                            int wmBase, int wnBase, int lane,
                                            float (&accH)[2][4][4],
                                            float (&accL)[2][4][4]){
    int g = lane >> 2, q = lane & 3;
    #pragma unroll
    for (int kk = 0; kk < 32; kk += 8){
        unsigned ah[2][4], al[2][4], bh[4][2], bl[4][2];
        #pragma unroll
        for (int mf = 0; mf < 2; mf++){
            int r = wmBase + mf*16 + g;
            const float* p = As + r*36 + kk + q;
            splitf(p[0],      ah[mf][0], al[mf][0]);
            splitf(p[8*36],   ah[mf][1], al[mf][1]);
            splitf(p[4],      ah[mf][2], al[mf][2]);
            splitf(p[8*36+4], ah[mf][3], al[mf][3]);
        }
        #pragma unroll
        for (int nf = 0; nf < 4; nf++){
            int nn = wnBase + nf*8 + g;
            const float* p = Bs + nn*36 + kk + q;
            splitf(p[0], bh[nf][0], bl[nf][0]);
            splitf(p[4], bh[nf][1], bl[nf][1]);
        }
        #pragma unroll
        for (int mf = 0; mf < 2; mf++)
            #pragma unroll
            for (int nf = 0; nf < 4; nf++){
                mma_tf32(accH[mf][nf], ah[mf], bh[nf]);
                mma_tf32(accL[mf][nf], ah[mf], bl[nf]);
                mma_tf32(accL[mf][nf], al[mf], bh[nf]);
            }
    }
}

// warp tile 16(m) x 32(n); A stride templated (36 staged, 260 for Cs). ILP-split.
template<int AS>
__device__ __forceinline__ void compute16(const float* __restrict__ Asl,
                                          const float* __restrict__ Bs,
                                          int wnBase, int lane,
                                          float (&accH)[4][4], float (&accL)[4][4]){
    int g = lane >> 2, q = lane & 3;
    #pragma unroll
    for (int kk = 0; kk < 32; kk += 8){
        unsigned ah[4], al[4], bh[4][2], bl[4][2];
        const float* p = Asl + g*AS + kk + q;
        splitf(p[0],      ah[0], al[0]);
        splitf(p[8*AS],   ah[1], al[1]);
        splitf(p[4],      ah[2], al[2]);
        splitf(p[8*AS+4], ah[3], al[3]);
        #pragma unroll
        for (int nf = 0; nf < 4; nf++){
            const float* pb = Bs + (wnBase + nf*8 + g)*36 + kk + q;
            splitf(pb[0], bh[nf][0], bl[nf][0]);
            splitf(pb[4], bh[nf][1], bl[nf][1]);
        }
        #pragma unroll
        for (int nf = 0; nf < 4; nf++){
            mma_tf32(accH[nf], ah, bh[nf]);
            mma_tf32(accL[nf], ah, bl[nf]);
            mma_tf32(accL[nf], al, bh[nf]);
        }
    }
}

// ---------------- 1) pooled mean (split per launch) --------------------------
__global__ void __launch_bounds__(256) pool_kernel(const float* __restrict__ hid, int base){
    int b = base + blockIdx.x;
    const float4* p = reinterpret_cast<const float4*>(hid + (size_t)b*S_*H_) + threadIdx.x;
    float ax=0.f,ay=0.f,az=0.f,aw=0.f;
    float bx=0.f,by=0.f,bz=0.f,bw=0.f;
    #pragma unroll 4
    for (int s=0; s<S_; s+=2){
        float4 v0 = p[(size_t)s*(H_/4)];
        float4 v1 = p[(size_t)(s+1)*(H_/4)];
        ax+=v0.x; ay+=v0.y; az+=v0.z; aw+=v0.w;
        bx+=v1.x; by+=v1.y; bz+=v1.z; bw+=v1.w;
    }
    float4 r;
    r.x=(ax+bx)*(1.f/S_); r.y=(ay+by)*(1.f/S_);
    r.z=(az+bz)*(1.f/S_); r.w=(aw+bw)*(1.f/S_);
    reinterpret_cast<float4*>(g_pooled + (size_t)b*H_)[threadIdx.x] = r;
}

// ---------------- 2) router + top-4 + softmax --------------------------------
__global__ void __launch_bounds__(512) router_topk_kernel(const float* __restrict__ hid,
                                                          const float* __restrict__ rW,
                                                          const float* __restrict__ rb){
    __shared__ float cls[H_];
    __shared__ float lg[E_];
    int b = blockIdx.x, tid = threadIdx.x;
    cls[tid]       = hid[(size_t)b*S_*H_ + tid];
    cls[tid + 512] = hid[(size_t)b*S_*H_ + tid + 512];
    __syncthreads();
    int w = tid >> 5, lane = tid & 31;
    float s = 0.f;
    const float* wr = rW + w*H_;
    #pragma unroll 8
    for (int j=lane; j<H_; j+=32) s += cls[j]*wr[j];
    #pragma unroll
    for (int o=16;o>0;o>>=1) s += __shfl_xor_sync(0xffffffffu, s, o);
    if (lane==0) lg[w] = s + rb[w];
    __syncthreads();
    if (tid==0){
        float v[E_];
        #pragma unroll
        for (int i=0;i<E_;i++) v[i]=lg[i];
        int   idxs[K_]; float vals[K_];
        for (int k=0;k<K_;k++){
            int bi=0; float bv=-3.0e38f;
            #pragma unroll
            for (int i=0;i<E_;i++){ if (v[i]>bv){ bv=v[i]; bi=i; } }
            idxs[k]=bi; vals[k]=bv; v[bi]=-3.0e38f;
        }
        float m = vals[0], ssum=0.f, wv[K_];
        for (int k=0;k<K_;k++){ wv[k]=expf(vals[k]-m); ssum+=wv[k]; }
        float inv = 1.f/ssum;
        for (int k=0;k<K_;k++){ g_topi[b*K_+k]=idxs[k]; g_topw[b*K_+k]=wv[k]*inv; }
    }
}

// ---------------- 3) gather per split (single block, smem counters) ----------
__global__ void __launch_bounds__(1024) gather_kernel(int half, int tokBase, int nTok){
    __shared__ int cnt[E_];
    int t = threadIdx.x;
    if (t < E_) cnt[t] = 0;
    __syncthreads();
    int total = nTok*K_;
    for (int i=t; i<total; i+=1024){
        int idx = tokBase*K_ + i;
        int e = g_topi[idx];
        int pos = atomicAdd(&cnt[e], 1);
        g_tok [(half*E_+e)*B_+pos] = idx >> 2;
        g_slot[(half*E_+e)*B_+pos] = idx & 3;
    }
    __syncthreads();
    if (t < E_) g_cnt[half*E_+t] = cnt[t];
}

// ---------------- 4) dense head: t = tanh(cls @ dW^T + db) -------------------
__global__ void __launch_bounds__(128) dense_tanh_kernel(const float* __restrict__ hid,
                                                         const float* __restrict__ W,
                                                         const float* __restrict__ bias){
    __shared__ float As[2][64*36];
    __shared__ float Bs[2][64*36];
    int t = threadIdx.x, lane = t & 31, warp = t >> 5;
    int wm = warp >> 1, wn = warp & 1;
    int m0 = blockIdx.y*64, n0 = blockIdx.x*64;
    int lr = t >> 3, lc = (t & 7)*4;
    float accH[2][4][4], accL[2][4][4];
    #pragma unroll
    for (int i=0;i<2;i++)
        #pragma unroll
        for (int j=0;j<4;j++)
            #pragma unroll
            for (int k=0;k<4;k++){ accH[i][j][k]=0.f; accL[i][j][k]=0.f; }

    auto load = [&](int s, int k0){
        #pragma unroll
        for (int i=0;i<4;i++){
            int row = lr + 16*i;
            cp16(&As[s][row*36+lc], hid + (size_t)(m0+row)*S_*H_ + k0 + lc);
            cp16(&Bs[s][row*36+lc], W   + (size_t)(n0+row)*H_   + k0 + lc);
        }
    };
    load(0, 0); cp_commit();
    for (int it=0; it<32; it++){
        if (it+1 < 32){ load((it+1)&1, (it+1)*32); cp_commit(); cp_wait1(); }
        else cp_wait0();
        __syncthreads();
        compute_raw(As[it&1], Bs[it&1], wm*32, wn*32, lane, accH, accL);
        __syncthreads();
    }
    int g = lane>>2, q = lane&3;
    #pragma unroll
    for (int nf=0;nf<4;nf++){
        int col = n0 + wn*32 + nf*8 + 2*q;
        float2 bb = *(const float2*)&bias[col];
        #pragma unroll
        for (int mf=0;mf<2;mf++){
            int row = m0 + wm*32 + mf*16 + g;
            float2 o0, o1;
            o0.x = tanhf(accH[mf][nf][0]+accL[mf][nf][0]+bb.x);
            o0.y = tanhf(accH[mf][nf][1]+accL[mf][nf][1]+bb.y);
            o1.x = tanhf(accH[mf][nf][2]+accL[mf][nf][2]+bb.x);
            o1.y = tanhf(accH[mf][nf][3]+accL[mf][nf][3]+bb.y);
            *(float2*)&g_t[(size_t)row*H_ + col]     = o0;
            *(float2*)&g_t[(size_t)(row+8)*H_ + col] = o1;
        }
    }
}

// ---------------- 5) orig = t @ out_W^T + out_b ------------------------------
__global__ void __launch_bounds__(256) orig_kernel(const float* __restrict__ oW,
                                                   const float* __restrict__ ob){
    int w = threadIdx.x >> 5, lane = threadIdx.x & 31;
    int b = blockIdx.x*8 + w;
    const float* t = g_t + (size_t)b*H_;
    for (int c=0;c<C_;c++){
        float s=0.f;
        const float* wr = oW + c*H_;
        #pragma unroll 8
        for (int j=lane; j<H_; j+=32) s += t[j]*wr[j];
        #pragma unroll
        for (int o=16;o>0;o>>=1) s += __shfl_xor_sync(0xffffffffu, s, o);
        if (lane==0) g_orig[b*C_+c] = s + ob[c];
    }
}

// ---------------- 6) fused expert (per split): GEMM1+LN+GELU+GEMM2+proj ------
// 16 gathered rows x 256 cols per block; 256 threads (8 warps, warp 16x32).
__global__ void __launch_bounds__(256) expert_fused_kernel(const float* __restrict__ eW1,
                                                           const float* __restrict__ eb1,
                                                           const float* __restrict__ eg,
                                                           const float* __restrict__ ebt,
                                                           const float* __restrict__ eW2,
                                                           const float* __restrict__ eb2,
                                                           const float* __restrict__ pW,
                                                           const float* __restrict__ pb,
                                                           int half){
    extern __shared__ float sm[];
    float* As0 = sm;                    // 16*36
    float* As1 = sm + 576;
    float* Bs0 = sm + 1152;             // 256*36
    float* Bs1 = sm + 1152 + 9216;
    float* Cs  = sm + 19584;            // 16 x 260
    __shared__ int toks[16], slots[16];
    int e = blockIdx.y;
    int n = g_cnt[half*E_+e];
    int r0 = blockIdx.x*16;
    if (r0 >= n) return;
    const int* tokb  = g_tok  + (half*E_+e)*B_;
    const int* slotb = g_slot + (half*E_+e)*B_;
    int t = threadIdx.x, lane = t & 31, warp = t >> 5;
    if (t < 16){
        int rc = min(r0 + t, n-1);
        toks[t]  = tokb [rc];
        slots[t] = slotb[rc];
    }
    __syncthreads();
    int lr = t >> 3, lc = (t & 7)*4;
    float accH[4][4], accL[4][4];
    #pragma unroll
    for (int i=0;i<4;i++)
        #pragma unroll
        for (int j=0;j<4;j++){ accH[i][j]=0.f; accL[i][j]=0.f; }

    const float* w1 = eW1 + (size_t)e*HE_*H_;
    const float* arow = g_pooled + (size_t)toks[lr & 15]*H_ + lc;
    auto load1 = [&](float* Asb, float* Bsb, int k0){
        if (t < 128) cp16(&Asb[lr*36+lc], arow + k0);
        #pragma unroll
        for (int i=0;i<8;i++){
            int row = lr + 32*i;
            cp16(&Bsb[row*36+lc], w1 + (size_t)row*H_ + k0 + lc);
        }
    };
    // ---- phase 1 mainloop (K=1024, 32 iters, 2-stage) ----
    load1(As0, Bs0, 0); cp_commit();
    for (int it=0; it<32; it++){
        if (it+1 < 32){
            if ((it+1)&1) load1(As1, Bs1, (it+1)*32); else load1(As0, Bs0, (it+1)*32);
            cp_commit(); cp_wait1();
        } else cp_wait0();
        __syncthreads();
        if (it&1) compute16<36>(As1, Bs1, warp*32, lane, accH, accL);
        else      compute16<36>(As0, Bs0, warp*32, lane, accH, accL);
        __syncthreads();
    }
    // ---- stage C tile into Cs ----
    int g = lane>>2, q = lane&3;
    #pragma unroll
    for (int nf=0;nf<4;nf++){
        int col = warp*32 + nf*8 + 2*q;
        float2 a; a.x=accH[nf][0]+accL[nf][0]; a.y=accH[nf][1]+accL[nf][1];
        float2 b; b.x=accH[nf][2]+accL[nf][2]; b.y=accH[nf][3]+accL[nf][3];
        *(float2*)&Cs[g*260 + col]     = a;
        *(float2*)&Cs[(g+8)*260 + col] = b;
    }
    __syncthreads();
    // ---- prefetch first eW2 tile while doing LN ----
    const float* w2 = eW2 + (size_t)e*HE_*HE_;
    auto load2 = [&](float* Bsb, int k0){
        #pragma unroll
        for (int i=0;i<8;i++){
            int row = lr + 32*i;
            cp16(&Bsb[row*36+lc], w2 + (size_t)row*HE_ + k0 + lc);
        }
    };
    load2(Bs0, 0); cp_commit();
    // ---- LN + GELU in place: 16 threads per row, 16 cols each ----
    {
        int row = t >> 4, j = t & 15;
        const float* b1 = eb1 + e*HE_;
        float s = 0.f, qs = 0.f;
        #pragma unroll
        for (int cc=0; cc<16; cc+=4){
            float4 v = *(float4*)&Cs[row*260 + j*16 + cc];
            float4 bb = *(const float4*)&b1[j*16 + cc];
            v.x+=bb.x; v.y+=bb.y; v.z+=bb.z; v.w+=bb.w;
            s  += v.x+v.y+v.z+v.w;
            qs += v.x*v.x+v.y*v.y+v.z*v.z+v.w*v.w;
        }
        #pragma unroll
        for (int o=1;o<16;o<<=1){
            s  += __shfl_xor_sync(0xffffffffu, s,  o);
            qs += __shfl_xor_sync(0xffffffffu, qs, o);
        }
        float m = s*(1.f/HE_);
        float var = qs*(1.f/HE_) - m*m;
        float rstd = rsqrtf(var + 1e-5f);
        const float* gp = eg  + e*HE_;
        const float* bp = ebt + e*HE_;
        #pragma unroll
        for (int cc=0; cc<16; cc+=4){
            float4 v = *(float4*)&Cs[row*260 + j*16 + cc];
            float4 bb = *(const float4*)&b1[j*16 + cc];
            float4 gg = *(const float4*)&gp[j*16 + cc];
            float4 bt = *(const float4*)&bp[j*16 + cc];
            float z0 = (v.x+bb.x-m)*rstd*gg.x + bt.x;
            float z1 = (v.y+bb.y-m)*rstd*gg.y + bt.y;
            float z2 = (v.z+bb.z-m)*rstd*gg.z + bt.z;
            float z3 = (v.w+bb.w-m)*rstd*gg.w + bt.w;
            float4 o;
            o.x = 0.5f*z0*(1.f+erff(z0*0.70710678118654752f));
            o.y = 0.5f*z1*(1.f+erff(z1*0.70710678118654752f));
            o.z = 0.5f*z2*(1.f+erff(z2*0.70710678118654752f));
            o.w = 0.5f*z3*(1.f+erff(z3*0.70710678118654752f));
            *(float4*)&Cs[row*260 + j*16 + cc] = o;
        }
    }
    __syncthreads();
    // ---- phase 2 mainloop (K=256, 8 iters, 2-stage; A = Cs, stride 260) ----
    float acc2H[4][4], acc2L[4][4];
    #pragma unroll
    for (int i=0;i<4;i++)
        #pragma unroll
        for (int j=0;j<4;j++){ acc2H[i][j]=0.f; acc2L[i][j]=0.f; }
    for (int it=0; it<8; it++){
        if (it+1 < 8){
            if ((it+1)&1) load2(Bs1, (it+1)*32); else load2(Bs0, (it+1)*32);
            cp_commit(); cp_wait1();
        } else cp_wait0();
        __syncthreads();
        if (it&1) compute16<260>(Cs + it*32, Bs1, warp*32, lane, acc2H, acc2L);
        else      compute16<260>(Cs + it*32, Bs0, warp*32, lane, acc2H, acc2L);
        __syncthreads();
    }
    // ---- stage phase-2 C tile (overwrite Cs) ----
    #pragma unroll
    for (int nf=0;nf<4;nf++){
        int col = warp*32 + nf*8 + 2*q;
        float2 a; a.x=acc2H[nf][0]+acc2L[nf][0]; a.y=acc2H[nf][1]+acc2L[nf][1];
        float2 b; b.x=acc2H[nf][2]+acc2L[nf][2]; b.y=acc2H[nf][3]+acc2L[nf][3];
        *(float2*)&Cs[g*260 + col]     = a;
        *(float2*)&Cs[(g+8)*260 + col] = b;
    }
    __syncthreads();
    // ---- proj epilogue: 16 threads/row, 16 cols each -> C=3 ----
    {
        int row = t >> 4, j = t & 15;
        int gr = r0 + row;
        const float* b2 = eb2 + e*HE_;
        float p0=0.f, p1=0.f, p2=0.f;
        #pragma unroll
        for (int cc=0; cc<16; cc+=4){
            float4 v = *(float4*)&Cs[row*260 + j*16 + cc];
            float4 bb = *(const float4*)&b2[j*16 + cc];
            v.x+=bb.x; v.y+=bb.y; v.z+=bb.z; v.w+=bb.w;
            float4 w0 = *(const float4*)&pW[0*HE_ + j*16 + cc];
            float4 w1p = *(const float4*)&pW[1*HE_ + j*16 + cc];
            float4 w2p = *(const float4*)&pW[2*HE_ + j*16 + cc];
            p0 += v.x*w0.x + v.y*w0.y + v.z*w0.z + v.w*w0.w;
            p1 += v.x*w1p.x + v.y*w1p.y + v.z*w1p.z + v.w*w1p.w;
            p2 += v.x*w2p.x + v.y*w2p.y + v.z*w2p.z + v.w*w2p.w;
        }
        #pragma unroll
        for (int o=1;o<16;o<<=1){
            p0 += __shfl_xor_sync(0xffffffffu, p0, o);
            p1 += __shfl_xor_sync(0xffffffffu, p1, o);
            p2 += __shfl_xor_sync(0xffffffffu, p2, o);
        }
        if (j == 0 && gr < n){
            int b = toks[row], sl = slots[row];
            float* o = &g_el[(b*K_+sl)*C_];
            o[0] = p0 + pb[0];
            o[1] = p1 + pb[1];
            o[2] = p2 + pb[2];
        }
    }
}

// ---------------- 8) final head ---------------------------------------------
__global__ void __launch_bounds__(256) final_kernel(const float* __restrict__ f1W,
                                                    const float* __restrict__ f1b,
                                                    const float* __restrict__ fg,
                                                    const float* __restrict__ fbt,
                                                    const float* __restrict__ f2W,
                                                    const float* __restrict__ f2b,
                                                    float* __restrict__ out){
    int b = blockIdx.x*blockDim.x + threadIdx.x;
    if (b >= B_) return;
    float comb[2*C_];
    #pragma unroll
    for (int c=0;c<C_;c++) comb[c] = g_orig[b*C_+c];
    float moe[C_]={0.f,0.f,0.f};
    #pragma unroll
    for (int k=0;k<K_;k++){
        float w = g_topw[b*K_+k];
        const float* el = &g_el[(b*K_+k)*C_];
        #pragma unroll
        for (int c=0;c<C_;c++) moe[c] += w*el[c];
    }
    #pragma unroll
    for (int c=0;c<C_;c++) comb[C_+c]=moe[c];
    float y[C_];
    #pragma unroll
    for (int c=0;c<C_;c++){
        float s = f1b[c];
        #pragma unroll
        for (int jj=0;jj<2*C_;jj++) s += comb[jj]*f1W[c*(2*C_)+jj];
        y[c]=s;
    }
    float m = (y[0]+y[1]+y[2])*(1.f/3.f);
    float d0=y[0]-m, d1=y[1]-m, d2=y[2]-m;
    float var = (d0*d0+d1*d1+d2*d2)*(1.f/3.f);
    float rs = rsqrtf(var + 1e-5f);
    float z[C_];
    #pragma unroll
    for (int c=0;c<C_;c++) z[c] = fmaxf(0.f, (y[c]-m)*rs*fg[c] + fbt[c]);
    #pragma unroll
    for (int c2=0;c2<C_;c2++){
        float s = f2b[c2];
        #pragma unroll
        for (int c=0;c<C_;c++) s += z[c]*f2W[c2*C_+c];
        out[b*C_+c2] = s;
    }
}

// ---------------- streams/events (host-side objects, created once) -----------
struct SideStreams {
    cudaStream_t sB, sC, sE;
    cudaEvent_t  evFork, evJC, evG0, evG1, evP0, evE0;
    SideStreams(){
        cudaStreamCreateWithFlags(&sB, cudaStreamNonBlocking);
        cudaStreamCreateWithFlags(&sC, cudaStreamNonBlocking);
        cudaStreamCreateWithFlags(&sE, cudaStreamNonBlocking);
        cudaEventCreateWithFlags(&evFork, cudaEventDisableTiming);
        cudaEventCreateWithFlags(&evJC,   cudaEventDisableTiming);
        cudaEventCreateWithFlags(&evG0,   cudaEventDisableTiming);
        cudaEventCreateWithFlags(&evG1,   cudaEventDisableTiming);
        cudaEventCreateWithFlags(&evP0,   cudaEventDisableTiming);
        cudaEventCreateWithFlags(&evE0,   cudaEventDisableTiming);
    }
};
static SideStreams g_ss;

// ---------------- launch -----------------------------------------------------
extern "C" void kernel_launch(void* const* d_in, const int* in_sizes, int n_in,
                              void* d_out, int out_size){
    const float* hid = (const float*)d_in[0];
    const float* rW  = (const float*)d_in[1];
    const float* rb  = (const float*)d_in[2];
    const float* eW1 = (const float*)d_in[3];
    const float* eb1 = (const float*)d_in[4];
    const float* eg  = (const float*)d_in[5];
    const float* ebt = (const float*)d_in[6];
    const float* eW2 = (const float*)d_in[7];
    const float* eb2 = (const float*)d_in[8];
    const float* pW  = (const float*)d_in[9];
    const float* pb  = (const float*)d_in[10];
    const float* dW  = (const float*)d_in[11];
    const float* db  = (const float*)d_in[12];
    const float* oW  = (const float*)d_in[13];
    const float* ob  = (const float*)d_in[14];
    const float* f1W = (const float*)d_in[15];
    const float* f1b = (const float*)d_in[16];
    const float* fg  = (const float*)d_in[17];
    const float* fbt = (const float*)d_in[18];
    const float* f2W = (const float*)d_in[19];
    const float* f2b = (const float*)d_in[20];
    float* out = (float*)d_out;

    const int DSM_EXP = (2*16*36 + 2*256*36 + 16*260)*4;  // 94976 B
    cudaFuncSetAttribute(expert_fused_kernel, cudaFuncAttributeMaxDynamicSharedMemorySize, DSM_EXP);

    // fork branches
    cudaEventRecord(g_ss.evFork, 0);
    cudaStreamWaitEvent(g_ss.sB, g_ss.evFork, 0);
    cudaStreamWaitEvent(g_ss.sC, g_ss.evFork, 0);

    // main stream: pool split 0 (640 rows), then split 1 (384 rows)
    pool_kernel<<<H0_, 256>>>(hid, 0);
    cudaEventRecord(g_ss.evP0, 0);
    pool_kernel<<<H1_, 256>>>(hid, H0_);

    // branch B: router (cls rows only) + per-split gathers
    router_topk_kernel<<<B_, 512, 0, g_ss.sB>>>(hid, rW, rb);
    gather_kernel<<<1, 1024, 0, g_ss.sB>>>(0, 0,   H0_);
    cudaEventRecord(g_ss.evG0, g_ss.sB);
    gather_kernel<<<1, 1024, 0, g_ss.sB>>>(1, H0_, H1_);
    cudaEventRecord(g_ss.evG1, g_ss.sB);

    // branch C: dense head + orig
    dense_tanh_kernel<<<dim3(16,16), 128, 0, g_ss.sC>>>(hid, dW, db);
    orig_kernel<<<B_/8, 256, 0, g_ss.sC>>>(oW, ob);
    cudaEventRecord(g_ss.evJC, g_ss.sC);

    // stream E: expert split 0 overlapped with pool split 1
    cudaStreamWaitEvent(g_ss.sE, g_ss.evP0, 0);
    cudaStreamWaitEvent(g_ss.sE, g_ss.evG0, 0);
    expert_fused_kernel<<<dim3(H0_/16, E_), 256, DSM_EXP, g_ss.sE>>>(
        eW1, eb1, eg, ebt, eW2, eb2, pW, pb, 0);
    cudaEventRecord(g_ss.evE0, g_ss.sE);

    // main: expert split 1 after pool split 1 (+gather 1)
    cudaStreamWaitEvent(0, g_ss.evG1, 0);
    expert_fused_kernel<<<dim3(H1_/16, E_), 256, DSM_EXP>>>(
        eW1, eb1, eg, ebt, eW2, eb2, pW, pb, 1);

    // final: needs expert split 0 (stream E), orig (stream C), split 1 (main)
    cudaStreamWaitEvent(0, g_ss.evE0, 0);
    cudaStreamWaitEvent(0, g_ss.evJC, 0);
    final_kernel<<<B_/256, 256>>>(f1W, f1b, fg, fbt, f2W, f2b, out);
}